// round 1
// baseline (speedup 1.0000x reference)
#include <cuda_runtime.h>
#include <cuda_bf16.h>

// ---------------------------------------------------------------------------
// Problem constants
// ---------------------------------------------------------------------------
constexpr long NV0 = 300000, NV1 = 98304, NV2 = 12288, NV3 = 1536, NV4 = 192;
constexpr long NE0 = 3600000, NE1 = 786432, NE2 = 196608, NE3 = 24576, NE4 = 3072;

// Scratch layout (floats). Zero-region first so a single kernel clears it.
constexpr long O_G1 = 0,            S_G1 = NV0 * 24;
constexpr long O_G2 = O_G1 + S_G1,  S_G2 = NV1 * 144;
constexpr long O_G3 = O_G2 + S_G2,  S_G3 = NV2 * 528;
constexpr long O_G4 = O_G3 + S_G3,  S_G4 = NV3 * 1040;
constexpr long O_G5 = O_G4 + S_G4,  S_G5 = NV4 * 1040;
constexpr long O_DEG1 = O_G5 + S_G5;
constexpr long O_DEG2 = O_DEG1 + NV0;
constexpr long O_DEG3 = O_DEG2 + NV1;
constexpr long O_DEG4 = O_DEG3 + NV2;
constexpr long O_DEG5 = O_DEG4 + NV3;
constexpr long O_X1P = O_DEG5 + NV4;
constexpr long O_X2P = O_X1P + NV1 * 16;
constexpr long O_X3P = O_X2P + NV2 * 64;
constexpr long O_X4P = O_X3P + NV3 * 128;
constexpr long O_P1P = O_X4P + NV4 * 128;
constexpr long O_P2P = O_P1P + NV1 * 3;
constexpr long O_P3P = O_P2P + NV2 * 3;
constexpr long O_P4P = O_P3P + NV3 * 3;
constexpr long O_CNT1 = O_P4P + NV4 * 3;
constexpr long O_CNT2 = O_CNT1 + NV1;
constexpr long O_CNT3 = O_CNT2 + NV2;
constexpr long O_CNT4 = O_CNT3 + NV3;
constexpr long ZERO_N = O_CNT4 + NV4;            // everything below here is zeroed each run
constexpr long O_FC0 = ZERO_N;
constexpr long O_H1  = O_FC0 + NV0 * 3;
constexpr long O_FC1 = O_H1 + NV0 * 16;
constexpr long O_H2  = O_FC1 + NV1 * 18;
constexpr long O_FC2 = O_H2 + NV1 * 64;
constexpr long O_H3  = O_FC2 + NV2 * 66;
constexpr long O_FC3 = O_H3 + NV2 * 128;
constexpr long O_H4  = O_FC3 + NV3 * 130;
constexpr long O_FC4 = O_H4 + NV3 * 128;
constexpr long O_H5  = O_FC4 + NV4 * 130;
constexpr long TOTAL_N = O_H5 + NV4 * 128;

__device__ float g_buf[TOTAL_N];

// ---------------------------------------------------------------------------
// Zero kernel (float4, grid-stride)
// ---------------------------------------------------------------------------
__global__ void zero_kernel(float* __restrict__ p, long n4) {
    float4* p4 = reinterpret_cast<float4*>(p);
    long i = (long)blockIdx.x * blockDim.x + threadIdx.x;
    long stride = (long)gridDim.x * blockDim.x;
    float4 z = make_float4(0.f, 0.f, 0.f, 0.f);
    for (; i < n4; i += stride) p4[i] = z;
}

// ---------------------------------------------------------------------------
// featcat: fc[v, 0..Ch-1] = h, fc[v, Ch..Ch+1] = pos.xy
// ---------------------------------------------------------------------------
__global__ void featcat_kernel(const float* __restrict__ h, int Ch,
                               const float* __restrict__ pos,
                               float* __restrict__ fc, int V) {
    int Cin = Ch + 2;
    long total = (long)V * Cin;
    long idx = (long)blockIdx.x * blockDim.x + threadIdx.x;
    if (idx >= total) return;
    int v = (int)(idx / Cin);
    int i = (int)(idx - (long)v * Cin);
    fc[idx] = (i < Ch) ? h[(long)v * Ch + i] : pos[(long)v * 3 + (i - Ch)];
}

// ---------------------------------------------------------------------------
// Edge scatter: G[dst, s*CIN+i] += basis_s(edge) * feat[src, i]; deg[dst] += 1
// One warp per edge -> the 8*CIN contiguous atomics coalesce per wavefront.
// ---------------------------------------------------------------------------
template <int CIN>
__global__ void __launch_bounds__(256)
edge_scatter_kernel(const int* __restrict__ e, long E,
                    const float* __restrict__ pos,
                    const float* __restrict__ feat,
                    float* __restrict__ G, float* __restrict__ deg,
                    float inv2mv) {
    const int* esrc = e;
    const int* edst = e + E;
    int lane = threadIdx.x & 31;
    long warpId = (long)blockIdx.x * (blockDim.x >> 5) + (threadIdx.x >> 5);
    long nWarps = (long)gridDim.x * (blockDim.x >> 5);
    for (long eid = warpId; eid < E; eid += nWarps) {
        int s = esrc[eid];
        int d = edst[eid];
        float p0 = fminf(fmaxf((pos[d * 3 + 0] - pos[s * 3 + 0]) * inv2mv + 0.5f, 0.f), 1.f);
        float p1 = fminf(fmaxf((pos[d * 3 + 1] - pos[s * 3 + 1]) * inv2mv + 0.5f, 0.f), 1.f);
        float p2 = fminf(fmaxf((pos[d * 3 + 2] - pos[s * 3 + 2]) * inv2mv + 0.5f, 0.f), 1.f);
        float q0 = 1.f - p0, q1 = 1.f - p1, q2 = 1.f - p2;
        const float* frow = feat + (long)s * CIN;
        float* grow = G + (long)d * (8 * CIN);
        #pragma unroll 4
        for (int k = lane; k < 8 * CIN; k += 32) {
            int ss = k / CIN;
            int i = k - ss * CIN;
            float b = ((ss & 1) ? p0 : q0) * ((ss & 2) ? p1 : q1) * ((ss & 4) ? p2 : q2);
            atomicAdd(grow + k, b * frow[i]);
        }
        if (lane == 0) atomicAdd(deg + d, 1.0f);
    }
}

// ---------------------------------------------------------------------------
// Node GEMM + root + bias + relu:
//   out[v,c] = relu( (G[v,:] @ Wk)[c] / max(deg,1) + (feat[v,:] @ Wr)[c] + b[c] )
// 32-row tile, 256 threads, K chunks of 32 through shared memory.
// ---------------------------------------------------------------------------
template <int CIN, int COUT>
__global__ void __launch_bounds__(256)
spline_out_kernel(const float* __restrict__ G, const float* __restrict__ deg,
                  const float* __restrict__ feat,
                  const float* __restrict__ Wk,   // [8*CIN, COUT]
                  const float* __restrict__ Wr,   // [CIN, COUT]
                  const float* __restrict__ bias, // [COUT]
                  float* __restrict__ out, int V) {
    constexpr int K1 = 8 * CIN;
    constexpr int TV = 32;
    constexpr int RS = 256 / COUT;   // row stride between a thread's rows
    constexpr int NR = TV / RS;      // rows per thread
    __shared__ float Gs[TV][33];
    __shared__ float Ws[32][COUT];
    int tid = threadIdx.x;
    int c = tid % COUT;
    int rg = tid / COUT;
    int v0 = blockIdx.x * TV;

    float acc[NR];
    float acc2[NR];
    #pragma unroll
    for (int r = 0; r < NR; r++) { acc[r] = 0.f; acc2[r] = 0.f; }

    // Pass 1: G @ Wk
    for (int k0 = 0; k0 < K1; k0 += 32) {
        #pragma unroll
        for (int j = 0; j < 4; j++) {
            int idx = tid + j * 256;
            int r = idx >> 5, kk = idx & 31;
            int v = v0 + r, k = k0 + kk;
            Gs[r][kk] = (v < V && k < K1) ? G[(long)v * K1 + k] : 0.f;
        }
        #pragma unroll
        for (int j = 0; j < (32 * COUT) / 256; j++) {
            int idx = tid + j * 256;
            int kk = idx / COUT, cc = idx % COUT;
            int k = k0 + kk;
            Ws[kk][cc] = (k < K1) ? Wk[(long)k * COUT + cc] : 0.f;
        }
        __syncthreads();
        #pragma unroll
        for (int kk = 0; kk < 32; kk++) {
            float w = Ws[kk][c];
            #pragma unroll
            for (int r = 0; r < NR; r++) acc[r] += Gs[rg + r * RS][kk] * w;
        }
        __syncthreads();
    }

    // Pass 2: feat @ Wr (root)
    for (int k0 = 0; k0 < CIN; k0 += 32) {
        #pragma unroll
        for (int j = 0; j < 4; j++) {
            int idx = tid + j * 256;
            int r = idx >> 5, kk = idx & 31;
            int v = v0 + r, k = k0 + kk;
            Gs[r][kk] = (v < V && k < CIN) ? feat[(long)v * CIN + k] : 0.f;
        }
        #pragma unroll
        for (int j = 0; j < (32 * COUT) / 256; j++) {
            int idx = tid + j * 256;
            int kk = idx / COUT, cc = idx % COUT;
            int k = k0 + kk;
            Ws[kk][cc] = (k < CIN) ? Wr[(long)k * COUT + cc] : 0.f;
        }
        __syncthreads();
        #pragma unroll
        for (int kk = 0; kk < 32; kk++) {
            float w = Ws[kk][c];
            #pragma unroll
            for (int r = 0; r < NR; r++) acc2[r] += Gs[rg + r * RS][kk] * w;
        }
        __syncthreads();
    }

    #pragma unroll
    for (int r = 0; r < NR; r++) {
        int row = rg + r * RS;
        int v = v0 + row;
        if (v < V) {
            float dg = fmaxf(deg[v], 1.0f);
            float o = acc[r] / dg + acc2[r] + bias[c];
            out[(long)v * COUT + c] = fmaxf(o, 0.f);
        }
    }
}

// ---------------------------------------------------------------------------
// Voxel pooling. One warp per input node. Max uses float-as-int atomicMax
// (valid: inputs are post-ReLU >= 0, buffers zero-initialized).
// ---------------------------------------------------------------------------
template <int C>
__global__ void __launch_bounds__(256)
pool_scatter_kernel(const float* __restrict__ h, const float* __restrict__ pos,
                    const int* __restrict__ batch, int cellsPrev,
                    int V_in, int nx, int ny, int nt,
                    float* __restrict__ xp, float* __restrict__ posSum,
                    float* __restrict__ cnt, int isMax) {
    int lane = threadIdx.x & 31;
    long w = (long)blockIdx.x * (blockDim.x >> 5) + (threadIdx.x >> 5);
    if (w >= V_in) return;
    int v = (int)w;
    int b = batch ? batch[v] : v / cellsPrev;
    float px = pos[(long)v * 3 + 0];
    float py = pos[(long)v * 3 + 1];
    float pt = pos[(long)v * 3 + 2];
    int ix = min(max((int)floorf(px * nx), 0), nx - 1);
    int iy = min(max((int)floorf(py * ny), 0), ny - 1);
    int it = min(max((int)floorf(pt * nt), 0), nt - 1);
    long cl = (((long)b * nx + ix) * ny + iy) * nt + it;
    for (int k = lane; k < C; k += 32) {
        float val = h[(long)v * C + k];
        if (isMax)
            atomicMax((int*)(xp + cl * C + k), __float_as_int(val));
        else
            atomicAdd(xp + cl * C + k, val);
    }
    if (lane < 3) atomicAdd(posSum + cl * 3 + lane, pos[(long)v * 3 + lane]);
    if (lane == 0) atomicAdd(cnt + cl, 1.0f);
}

template <int C>
__global__ void pool_finalize_kernel(float* __restrict__ xp, float* __restrict__ posSum,
                                     const float* __restrict__ cnt, int V, int isMean) {
    int v = blockIdx.x * blockDim.x + threadIdx.x;
    if (v >= V) return;
    float cn = fmaxf(cnt[v], 1.0f);
    float inv = 1.0f / cn;
    posSum[(long)v * 3 + 0] *= inv;
    posSum[(long)v * 3 + 1] *= inv;
    posSum[(long)v * 3 + 2] *= inv;
    if (isMean) {
        for (int k = 0; k < C; k++) xp[(long)v * C + k] *= inv;
    }
}

// ---------------------------------------------------------------------------
// Launch
// ---------------------------------------------------------------------------
static inline int cdiv(long a, long b) { return (int)((a + b - 1) / b); }

extern "C" void kernel_launch(void* const* d_in, const int* in_sizes, int n_in,
                              void* d_out, int out_size) {
    const float* x    = (const float*)d_in[0];
    const float* pos0 = (const float*)d_in[1];
    const int*   batch = (const int*)d_in[2];
    const int* e0 = (const int*)d_in[3];
    const int* e1 = (const int*)d_in[4];
    const int* e2 = (const int*)d_in[5];
    const int* e3 = (const int*)d_in[6];
    const int* e4 = (const int*)d_in[7];
    const float* W1 = (const float*)d_in[8];
    const float* R1 = (const float*)d_in[9];
    const float* b1 = (const float*)d_in[10];
    const float* W2 = (const float*)d_in[11];
    const float* R2 = (const float*)d_in[12];
    const float* b2 = (const float*)d_in[13];
    const float* W3 = (const float*)d_in[14];
    const float* R3 = (const float*)d_in[15];
    const float* b3 = (const float*)d_in[16];
    const float* W4 = (const float*)d_in[17];
    const float* R4 = (const float*)d_in[18];
    const float* b4 = (const float*)d_in[19];
    const float* W5 = (const float*)d_in[20];
    const float* R5 = (const float*)d_in[21];
    const float* b5 = (const float*)d_in[22];
    float* out = (float*)d_out;

    float* buf;
    cudaGetSymbolAddress((void**)&buf, g_buf);

    // Zero the scatter/pool accumulators
    zero_kernel<<<2048, 256>>>(buf, ZERO_N / 4);

    // ---------------- Layer 1: Cin=3 -> Cout=16, V=300000, E=3.6M ----------
    featcat_kernel<<<cdiv(NV0 * 3, 256), 256>>>(x, 1, pos0, buf + O_FC0, (int)NV0);
    edge_scatter_kernel<3><<<cdiv(NE0, 8), 256>>>(e0, NE0, pos0, buf + O_FC0,
                                                  buf + O_G1, buf + O_DEG1, 20.0f);
    spline_out_kernel<3, 16><<<cdiv(NV0, 32), 256>>>(buf + O_G1, buf + O_DEG1,
        buf + O_FC0, W1, R1, b1, buf + O_H1, (int)NV0);
    pool_scatter_kernel<16><<<cdiv(NV0, 8), 256>>>(buf + O_H1, pos0, batch, 0,
        (int)NV0, 64, 48, 8, buf + O_X1P, buf + O_P1P, buf + O_CNT1, 1);
    pool_finalize_kernel<16><<<cdiv(NV1, 256), 256>>>(buf + O_X1P, buf + O_P1P,
        buf + O_CNT1, (int)NV1, 0);

    // ---------------- Layer 2: Cin=18 -> Cout=64, V=98304, E=786432 --------
    featcat_kernel<<<cdiv(NV1 * 18, 256), 256>>>(buf + O_X1P, 16, buf + O_P1P,
        buf + O_FC1, (int)NV1);
    edge_scatter_kernel<18><<<cdiv(NE1, 8), 256>>>(e1, NE1, buf + O_P1P, buf + O_FC1,
                                                   buf + O_G2, buf + O_DEG2, 10.0f);
    spline_out_kernel<18, 64><<<cdiv(NV1, 32), 256>>>(buf + O_G2, buf + O_DEG2,
        buf + O_FC1, W2, R2, b2, buf + O_H2, (int)NV1);
    pool_scatter_kernel<64><<<cdiv(NV1, 8), 256>>>(buf + O_H2, buf + O_P1P,
        (const int*)nullptr, 64 * 48 * 8, (int)NV1, 32, 24, 4,
        buf + O_X2P, buf + O_P2P, buf + O_CNT2, 1);
    pool_finalize_kernel<64><<<cdiv(NV2, 256), 256>>>(buf + O_X2P, buf + O_P2P,
        buf + O_CNT2, (int)NV2, 0);

    // ---------------- Layer 3: Cin=66 -> Cout=128, V=12288, E=196608 -------
    featcat_kernel<<<cdiv(NV2 * 66, 256), 256>>>(buf + O_X2P, 64, buf + O_P2P,
        buf + O_FC2, (int)NV2);
    edge_scatter_kernel<66><<<cdiv(NE2, 8), 256>>>(e2, NE2, buf + O_P2P, buf + O_FC2,
                                                   buf + O_G3, buf + O_DEG3, 6.0f);
    spline_out_kernel<66, 128><<<cdiv(NV2, 32), 256>>>(buf + O_G3, buf + O_DEG3,
        buf + O_FC2, W3, R3, b3, buf + O_H3, (int)NV2);
    pool_scatter_kernel<128><<<cdiv(NV2, 8), 256>>>(buf + O_H3, buf + O_P2P,
        (const int*)nullptr, 32 * 24 * 4, (int)NV2, 16, 12, 2,
        buf + O_X3P, buf + O_P3P, buf + O_CNT3, 1);
    pool_finalize_kernel<128><<<cdiv(NV3, 256), 256>>>(buf + O_X3P, buf + O_P3P,
        buf + O_CNT3, (int)NV3, 0);

    // ---------------- Layer 4: Cin=130 -> Cout=128, V=1536, E=24576 --------
    featcat_kernel<<<cdiv(NV3 * 130, 256), 256>>>(buf + O_X3P, 128, buf + O_P3P,
        buf + O_FC3, (int)NV3);
    edge_scatter_kernel<130><<<cdiv(NE3, 8), 256>>>(e3, NE3, buf + O_P3P, buf + O_FC3,
                                                    buf + O_G4, buf + O_DEG4, 3.0f);
    spline_out_kernel<130, 128><<<cdiv(NV3, 32), 256>>>(buf + O_G4, buf + O_DEG4,
        buf + O_FC3, W4, R4, b4, buf + O_H4, (int)NV3);
    // out3 = h4
    cudaMemcpyAsync(out, buf + O_H4, NV3 * 128 * sizeof(float),
                    cudaMemcpyDeviceToDevice, 0);
    // pool 4: mean
    pool_scatter_kernel<128><<<cdiv(NV3, 8), 256>>>(buf + O_H4, buf + O_P3P,
        (const int*)nullptr, 16 * 12 * 2, (int)NV3, 8, 6, 1,
        buf + O_X4P, buf + O_P4P, buf + O_CNT4, 0);
    pool_finalize_kernel<128><<<cdiv(NV4, 256), 256>>>(buf + O_X4P, buf + O_P4P,
        buf + O_CNT4, (int)NV4, 1);

    // ---------------- Layer 5: Cin=130 -> Cout=128, V=192, E=3072 ----------
    featcat_kernel<<<cdiv(NV4 * 130, 256), 256>>>(buf + O_X4P, 128, buf + O_P4P,
        buf + O_FC4, (int)NV4);
    edge_scatter_kernel<130><<<cdiv(NE4, 8), 256>>>(e4, NE4, buf + O_P4P, buf + O_FC4,
                                                    buf + O_G5, buf + O_DEG5, 1.5f);
    spline_out_kernel<130, 128><<<cdiv(NV4, 32), 256>>>(buf + O_G5, buf + O_DEG5,
        buf + O_FC4, W5, R5, b5, buf + O_H5, (int)NV4);
    cudaMemcpyAsync(out + NV3 * 128, buf + O_H5, NV4 * 128 * sizeof(float),
                    cudaMemcpyDeviceToDevice, 0);
}

// round 2
// speedup vs baseline: 1.5583x; 1.5583x over previous
#include <cuda_runtime.h>
#include <cuda_bf16.h>

// ---------------------------------------------------------------------------
// Problem constants
// ---------------------------------------------------------------------------
constexpr long NV0 = 300000, NV1 = 98304, NV2 = 12288, NV3 = 1536, NV4 = 192;
constexpr long NE0 = 3600000, NE1 = 786432, NE2 = 196608, NE3 = 24576, NE4 = 3072;

// Scratch layout (floats). Zero-region first so a single kernel clears it.
constexpr long O_G1 = 0,            S_G1 = NV0 * 24;
constexpr long O_G2 = O_G1 + S_G1,  S_G2 = NV1 * 144;
constexpr long O_G3 = O_G2 + S_G2,  S_G3 = NV2 * 528;
constexpr long O_G4 = O_G3 + S_G3,  S_G4 = NV3 * 1040;
constexpr long O_G5 = O_G4 + S_G4,  S_G5 = NV4 * 1040;
constexpr long O_DEG1 = O_G5 + S_G5;
constexpr long O_DEG2 = O_DEG1 + NV0;
constexpr long O_DEG3 = O_DEG2 + NV1;
constexpr long O_DEG4 = O_DEG3 + NV2;
constexpr long O_DEG5 = O_DEG4 + NV3;
constexpr long O_X1P = O_DEG5 + NV4;
constexpr long O_X2P = O_X1P + NV1 * 16;
constexpr long O_X3P = O_X2P + NV2 * 64;
constexpr long O_X4P = O_X3P + NV3 * 128;
constexpr long O_P1P = O_X4P + NV4 * 128;
constexpr long O_P2P = O_P1P + NV1 * 3;
constexpr long O_P3P = O_P2P + NV2 * 3;
constexpr long O_P4P = O_P3P + NV3 * 3;
constexpr long O_CNT1 = O_P4P + NV4 * 3;
constexpr long O_CNT2 = O_CNT1 + NV1;
constexpr long O_CNT3 = O_CNT2 + NV2;
constexpr long O_CNT4 = O_CNT3 + NV3;
constexpr long ZERO_N = O_CNT4 + NV4;            // everything below here is zeroed each run
constexpr long O_FC0 = ZERO_N;
constexpr long O_H1  = O_FC0 + NV0 * 3;
constexpr long O_FC1 = O_H1 + NV0 * 16;
constexpr long O_H2  = O_FC1 + NV1 * 18;
constexpr long O_FC2 = O_H2 + NV1 * 64;
constexpr long O_H3  = O_FC2 + NV2 * 66;
constexpr long O_FC3 = O_H3 + NV2 * 128;
constexpr long O_H4  = O_FC3 + NV3 * 130;
constexpr long O_FC4 = O_H4 + NV3 * 128;
constexpr long O_H5  = O_FC4 + NV4 * 130;
constexpr long TOTAL_N = O_H5 + NV4 * 128;

__device__ __align__(16) float g_buf[TOTAL_N];

// ---------------------------------------------------------------------------
// Zero kernel (float4, grid-stride)
// ---------------------------------------------------------------------------
__global__ void zero_kernel(float* __restrict__ p, long n4) {
    float4* p4 = reinterpret_cast<float4*>(p);
    long i = (long)blockIdx.x * blockDim.x + threadIdx.x;
    long stride = (long)gridDim.x * blockDim.x;
    float4 z = make_float4(0.f, 0.f, 0.f, 0.f);
    for (; i < n4; i += stride) p4[i] = z;
}

// ---------------------------------------------------------------------------
// featcat: fc[v, 0..Ch-1] = h, fc[v, Ch..Ch+1] = pos.xy
// ---------------------------------------------------------------------------
__global__ void featcat_kernel(const float* __restrict__ h, int Ch,
                               const float* __restrict__ pos,
                               float* __restrict__ fc, int V) {
    int Cin = Ch + 2;
    long total = (long)V * Cin;
    long idx = (long)blockIdx.x * blockDim.x + threadIdx.x;
    if (idx >= total) return;
    int v = (int)(idx / Cin);
    int i = (int)(idx - (long)v * Cin);
    fc[idx] = (i < Ch) ? h[(long)v * Ch + i] : pos[(long)v * 3 + (i - Ch)];
}

// ---------------------------------------------------------------------------
// Edge scatter, vectorized: one thread per 4-float chunk of one edge's G row.
// Uses red.global.add.v4.f32 (sm_90+) -> 4x fewer RED lanes than scalar.
//   G[dst, s*CIN+i] += basis_s(edge) * feat[src, i];  deg[dst] += 1
// ---------------------------------------------------------------------------
template <int CIN>
__global__ void __launch_bounds__(256)
edge_scatter_v4(const int* __restrict__ e, long E,
                const float* __restrict__ pos,
                const float* __restrict__ feat,
                float* __restrict__ G, float* __restrict__ deg,
                float inv2mv) {
    constexpr int CH = (8 * CIN) / 4;      // v4 chunks per edge
    long total = E * CH;
    long t = (long)blockIdx.x * blockDim.x + threadIdx.x;
    long stride = (long)gridDim.x * blockDim.x;
    for (; t < total; t += stride) {
        long eid = t / CH;
        int ch = (int)(t - eid * CH);
        int s = e[eid];
        int d = e[E + eid];
        // all CH threads of the same edge hit the same pos words -> L1 broadcast
        float p0 = __saturatef((pos[d * 3 + 0] - pos[s * 3 + 0]) * inv2mv + 0.5f);
        float p1 = __saturatef((pos[d * 3 + 1] - pos[s * 3 + 1]) * inv2mv + 0.5f);
        float p2 = __saturatef((pos[d * 3 + 2] - pos[s * 3 + 2]) * inv2mv + 0.5f);
        float q0 = 1.f - p0, q1 = 1.f - p1, q2 = 1.f - p2;
        int k0 = ch * 4;
        float vv[4];
        #pragma unroll
        for (int j = 0; j < 4; j++) {
            int k = k0 + j;
            int ss = k / CIN;
            int i = k - ss * CIN;
            float b = ((ss & 1) ? p0 : q0) * ((ss & 2) ? p1 : q1) * ((ss & 4) ? p2 : q2);
            vv[j] = b * feat[(long)s * CIN + i];
        }
        float* addr = G + (long)d * (8 * CIN) + k0;   // 16B aligned: 8*CIN%4==0
        asm volatile("red.global.add.v4.f32 [%0], {%1, %2, %3, %4};"
                     :: "l"(addr), "f"(vv[0]), "f"(vv[1]), "f"(vv[2]), "f"(vv[3])
                     : "memory");
        if (ch == 0) atomicAdd(deg + d, 1.0f);
    }
}

// ---------------------------------------------------------------------------
// Layer-1 output: thread-per-node register kernel (CIN=3 -> 24 K, COUT=16).
//   out[v,c] = relu(G[v,:]@Wk / max(deg,1) + fc[v,:]@Wr + b)
// ---------------------------------------------------------------------------
__global__ void __launch_bounds__(256)
spline_out1_kernel(const float* __restrict__ G, const float* __restrict__ deg,
                   const float* __restrict__ fc,
                   const float* __restrict__ Wk,   // [24,16]
                   const float* __restrict__ Wr,   // [3,16]
                   const float* __restrict__ bias, // [16]
                   float* __restrict__ out, int V) {
    __shared__ float sWk[24][16];
    __shared__ float sWr[3][16];
    __shared__ float sb[16];
    int tid = threadIdx.x;
    for (int i = tid; i < 24 * 16; i += 256) sWk[i / 16][i % 16] = Wk[i];
    if (tid < 48) sWr[tid / 16][tid % 16] = Wr[tid];
    if (tid < 16) sb[tid] = bias[tid];
    __syncthreads();
    int v = blockIdx.x * 256 + tid;
    if (v >= V) return;
    float acc[16];
    #pragma unroll
    for (int c = 0; c < 16; c++) acc[c] = 0.f;
    const float4* g4 = reinterpret_cast<const float4*>(G + (long)v * 24);
    #pragma unroll
    for (int j = 0; j < 6; j++) {
        float4 g = g4[j];
        int k = j * 4;
        #pragma unroll
        for (int c = 0; c < 16; c++)
            acc[c] += g.x * sWk[k][c] + g.y * sWk[k + 1][c]
                    + g.z * sWk[k + 2][c] + g.w * sWk[k + 3][c];
    }
    float inv = 1.f / fmaxf(deg[v], 1.f);
    float f0 = fc[(long)v * 3 + 0], f1 = fc[(long)v * 3 + 1], f2 = fc[(long)v * 3 + 2];
    float4* o4 = reinterpret_cast<float4*>(out + (long)v * 16);
    #pragma unroll
    for (int j = 0; j < 4; j++) {
        float4 o;
        float* op = &o.x;
        #pragma unroll
        for (int u = 0; u < 4; u++) {
            int c = j * 4 + u;
            float val = acc[c] * inv + f0 * sWr[0][c] + f1 * sWr[1][c]
                      + f2 * sWr[2][c] + sb[c];
            op[u] = fmaxf(val, 0.f);
        }
        o4[j] = o;
    }
}

// ---------------------------------------------------------------------------
// Register-tiled GEMM for layers 2..5: TV rows x COUT cols per block,
// 256 threads (16x16), each thread NR x NC micro-tile. Gs stored transposed.
// ---------------------------------------------------------------------------
template <int CIN, int COUT, int TV>
__global__ void __launch_bounds__(256)
spline_gemm_kernel(const float* __restrict__ G, const float* __restrict__ deg,
                   const float* __restrict__ feat,
                   const float* __restrict__ Wk,   // [8*CIN, COUT]
                   const float* __restrict__ Wr,   // [CIN, COUT]
                   const float* __restrict__ bias, // [COUT]
                   float* __restrict__ out, int V) {
    constexpr int K1 = 8 * CIN;
    constexpr int NR = TV / 16;
    constexpr int NC = COUT / 16;
    __shared__ float Gs[32][TV + 1];
    __shared__ float Ws[32][COUT];
    int tid = threadIdx.x;
    int tx = tid & 15, ty = tid >> 4;
    int v0 = blockIdx.x * TV;
    float acc1[NR][NC];
    float acc2[NR][NC];
    #pragma unroll
    for (int r = 0; r < NR; r++)
        #pragma unroll
        for (int c = 0; c < NC; c++) { acc1[r][c] = 0.f; acc2[r][c] = 0.f; }

    // Pass 1: G @ Wk
    for (int k0 = 0; k0 < K1; k0 += 32) {
        #pragma unroll
        for (int j = 0; j < TV * 32 / 256; j++) {
            int idx = tid + j * 256;
            int r = idx >> 5, kk = idx & 31;
            int v = v0 + r, k = k0 + kk;
            Gs[kk][r] = (v < V && k < K1) ? G[(long)v * K1 + k] : 0.f;
        }
        #pragma unroll
        for (int j = 0; j < 32 * COUT / 256; j++) {
            int idx = tid + j * 256;
            int kk = idx / COUT, cc = idx - kk * COUT;
            int k = k0 + kk;
            Ws[kk][cc] = (k < K1) ? Wk[(long)k * COUT + cc] : 0.f;
        }
        __syncthreads();
        #pragma unroll
        for (int kk = 0; kk < 32; kk++) {
            float a[NR], b[NC];
            #pragma unroll
            for (int r = 0; r < NR; r++) a[r] = Gs[kk][ty + r * 16];
            #pragma unroll
            for (int c = 0; c < NC; c++) b[c] = Ws[kk][tx + c * 16];
            #pragma unroll
            for (int r = 0; r < NR; r++)
                #pragma unroll
                for (int c = 0; c < NC; c++) acc1[r][c] += a[r] * b[c];
        }
        __syncthreads();
    }

    // Pass 2: feat @ Wr (root)
    for (int k0 = 0; k0 < CIN; k0 += 32) {
        #pragma unroll
        for (int j = 0; j < TV * 32 / 256; j++) {
            int idx = tid + j * 256;
            int r = idx >> 5, kk = idx & 31;
            int v = v0 + r, k = k0 + kk;
            Gs[kk][r] = (v < V && k < CIN) ? feat[(long)v * CIN + k] : 0.f;
        }
        #pragma unroll
        for (int j = 0; j < 32 * COUT / 256; j++) {
            int idx = tid + j * 256;
            int kk = idx / COUT, cc = idx - kk * COUT;
            int k = k0 + kk;
            Ws[kk][cc] = (k < CIN) ? Wr[(long)k * COUT + cc] : 0.f;
        }
        __syncthreads();
        #pragma unroll
        for (int kk = 0; kk < 32; kk++) {
            float a[NR], b[NC];
            #pragma unroll
            for (int r = 0; r < NR; r++) a[r] = Gs[kk][ty + r * 16];
            #pragma unroll
            for (int c = 0; c < NC; c++) b[c] = Ws[kk][tx + c * 16];
            #pragma unroll
            for (int r = 0; r < NR; r++)
                #pragma unroll
                for (int c = 0; c < NC; c++) acc2[r][c] += a[r] * b[c];
        }
        __syncthreads();
    }

    #pragma unroll
    for (int r = 0; r < NR; r++) {
        int v = v0 + ty + r * 16;
        if (v < V) {
            float inv = 1.f / fmaxf(deg[v], 1.f);
            #pragma unroll
            for (int c = 0; c < NC; c++) {
                int col = tx + c * 16;
                float o = acc1[r][c] * inv + acc2[r][c] + bias[col];
                out[(long)v * COUT + col] = fmaxf(o, 0.f);
            }
        }
    }
}

// ---------------------------------------------------------------------------
// Voxel pooling. One warp per input node. Max uses float-as-int atomicMax
// (valid: inputs are post-ReLU >= 0, buffers zero-initialized).
// ---------------------------------------------------------------------------
template <int C>
__global__ void __launch_bounds__(256)
pool_scatter_kernel(const float* __restrict__ h, const float* __restrict__ pos,
                    const int* __restrict__ batch, int cellsPrev,
                    int V_in, int nx, int ny, int nt,
                    float* __restrict__ xp, float* __restrict__ posSum,
                    float* __restrict__ cnt, int isMax) {
    int lane = threadIdx.x & 31;
    long w = (long)blockIdx.x * (blockDim.x >> 5) + (threadIdx.x >> 5);
    if (w >= V_in) return;
    int v = (int)w;
    int b = batch ? batch[v] : v / cellsPrev;
    float px = pos[(long)v * 3 + 0];
    float py = pos[(long)v * 3 + 1];
    float pt = pos[(long)v * 3 + 2];
    int ix = min(max((int)floorf(px * nx), 0), nx - 1);
    int iy = min(max((int)floorf(py * ny), 0), ny - 1);
    int it = min(max((int)floorf(pt * nt), 0), nt - 1);
    long cl = (((long)b * nx + ix) * ny + iy) * nt + it;
    for (int k = lane; k < C; k += 32) {
        float val = h[(long)v * C + k];
        if (isMax)
            atomicMax((int*)(xp + cl * C + k), __float_as_int(val));
        else
            atomicAdd(xp + cl * C + k, val);
    }
    if (lane < 3) atomicAdd(posSum + cl * 3 + lane, pos[(long)v * 3 + lane]);
    if (lane == 0) atomicAdd(cnt + cl, 1.0f);
}

template <int C>
__global__ void pool_finalize_kernel(float* __restrict__ xp, float* __restrict__ posSum,
                                     const float* __restrict__ cnt, int V, int isMean) {
    int v = blockIdx.x * blockDim.x + threadIdx.x;
    if (v >= V) return;
    float cn = fmaxf(cnt[v], 1.0f);
    float inv = 1.0f / cn;
    posSum[(long)v * 3 + 0] *= inv;
    posSum[(long)v * 3 + 1] *= inv;
    posSum[(long)v * 3 + 2] *= inv;
    if (isMean) {
        for (int k = 0; k < C; k++) xp[(long)v * C + k] *= inv;
    }
}

// ---------------------------------------------------------------------------
// Launch
// ---------------------------------------------------------------------------
static inline int cdiv(long a, long b) { return (int)((a + b - 1) / b); }
static inline int scat_grid(long total) {
    int g = cdiv(total, 256);
    return g > 4096 ? 4096 : g;
}

extern "C" void kernel_launch(void* const* d_in, const int* in_sizes, int n_in,
                              void* d_out, int out_size) {
    const float* x    = (const float*)d_in[0];
    const float* pos0 = (const float*)d_in[1];
    const int*   batch = (const int*)d_in[2];
    const int* e0 = (const int*)d_in[3];
    const int* e1 = (const int*)d_in[4];
    const int* e2 = (const int*)d_in[5];
    const int* e3 = (const int*)d_in[6];
    const int* e4 = (const int*)d_in[7];
    const float* W1 = (const float*)d_in[8];
    const float* R1 = (const float*)d_in[9];
    const float* b1 = (const float*)d_in[10];
    const float* W2 = (const float*)d_in[11];
    const float* R2 = (const float*)d_in[12];
    const float* b2 = (const float*)d_in[13];
    const float* W3 = (const float*)d_in[14];
    const float* R3 = (const float*)d_in[15];
    const float* b3 = (const float*)d_in[16];
    const float* W4 = (const float*)d_in[17];
    const float* R4 = (const float*)d_in[18];
    const float* b4 = (const float*)d_in[19];
    const float* W5 = (const float*)d_in[20];
    const float* R5 = (const float*)d_in[21];
    const float* b5 = (const float*)d_in[22];
    float* out = (float*)d_out;

    float* buf;
    cudaGetSymbolAddress((void**)&buf, g_buf);

    // Zero the scatter/pool accumulators
    zero_kernel<<<2048, 256>>>(buf, ZERO_N / 4);

    // ---------------- Layer 1: Cin=3 -> Cout=16, V=300000, E=3.6M ----------
    featcat_kernel<<<cdiv(NV0 * 3, 256), 256>>>(x, 1, pos0, buf + O_FC0, (int)NV0);
    edge_scatter_v4<3><<<scat_grid(NE0 * 6), 256>>>(e0, NE0, pos0, buf + O_FC0,
                                                    buf + O_G1, buf + O_DEG1, 20.0f);
    spline_out1_kernel<<<cdiv(NV0, 256), 256>>>(buf + O_G1, buf + O_DEG1,
        buf + O_FC0, W1, R1, b1, buf + O_H1, (int)NV0);
    pool_scatter_kernel<16><<<cdiv(NV0, 8), 256>>>(buf + O_H1, pos0, batch, 0,
        (int)NV0, 64, 48, 8, buf + O_X1P, buf + O_P1P, buf + O_CNT1, 1);
    pool_finalize_kernel<16><<<cdiv(NV1, 256), 256>>>(buf + O_X1P, buf + O_P1P,
        buf + O_CNT1, (int)NV1, 0);

    // ---------------- Layer 2: Cin=18 -> Cout=64, V=98304, E=786432 --------
    featcat_kernel<<<cdiv(NV1 * 18, 256), 256>>>(buf + O_X1P, 16, buf + O_P1P,
        buf + O_FC1, (int)NV1);
    edge_scatter_v4<18><<<scat_grid(NE1 * 36), 256>>>(e1, NE1, buf + O_P1P, buf + O_FC1,
                                                      buf + O_G2, buf + O_DEG2, 10.0f);
    spline_gemm_kernel<18, 64, 64><<<cdiv(NV1, 64), 256>>>(buf + O_G2, buf + O_DEG2,
        buf + O_FC1, W2, R2, b2, buf + O_H2, (int)NV1);
    pool_scatter_kernel<64><<<cdiv(NV1, 8), 256>>>(buf + O_H2, buf + O_P1P,
        (const int*)nullptr, 64 * 48 * 8, (int)NV1, 32, 24, 4,
        buf + O_X2P, buf + O_P2P, buf + O_CNT2, 1);
    pool_finalize_kernel<64><<<cdiv(NV2, 256), 256>>>(buf + O_X2P, buf + O_P2P,
        buf + O_CNT2, (int)NV2, 0);

    // ---------------- Layer 3: Cin=66 -> Cout=128, V=12288, E=196608 -------
    featcat_kernel<<<cdiv(NV2 * 66, 256), 256>>>(buf + O_X2P, 64, buf + O_P2P,
        buf + O_FC2, (int)NV2);
    edge_scatter_v4<66><<<scat_grid(NE2 * 132), 256>>>(e2, NE2, buf + O_P2P, buf + O_FC2,
                                                       buf + O_G3, buf + O_DEG3, 6.0f);
    spline_gemm_kernel<66, 128, 64><<<cdiv(NV2, 64), 256>>>(buf + O_G3, buf + O_DEG3,
        buf + O_FC2, W3, R3, b3, buf + O_H3, (int)NV2);
    pool_scatter_kernel<128><<<cdiv(NV2, 8), 256>>>(buf + O_H3, buf + O_P2P,
        (const int*)nullptr, 32 * 24 * 4, (int)NV2, 16, 12, 2,
        buf + O_X3P, buf + O_P3P, buf + O_CNT3, 1);
    pool_finalize_kernel<128><<<cdiv(NV3, 256), 256>>>(buf + O_X3P, buf + O_P3P,
        buf + O_CNT3, (int)NV3, 0);

    // ---------------- Layer 4: Cin=130 -> Cout=128, V=1536, E=24576 --------
    featcat_kernel<<<cdiv(NV3 * 130, 256), 256>>>(buf + O_X3P, 128, buf + O_P3P,
        buf + O_FC3, (int)NV3);
    edge_scatter_v4<130><<<scat_grid(NE3 * 260), 256>>>(e3, NE3, buf + O_P3P, buf + O_FC3,
                                                        buf + O_G4, buf + O_DEG4, 3.0f);
    spline_gemm_kernel<130, 128, 32><<<cdiv(NV3, 32), 256>>>(buf + O_G4, buf + O_DEG4,
        buf + O_FC3, W4, R4, b4, buf + O_H4, (int)NV3);
    // out3 = h4
    cudaMemcpyAsync(out, buf + O_H4, NV3 * 128 * sizeof(float),
                    cudaMemcpyDeviceToDevice, 0);
    // pool 4: mean
    pool_scatter_kernel<128><<<cdiv(NV3, 8), 256>>>(buf + O_H4, buf + O_P3P,
        (const int*)nullptr, 16 * 12 * 2, (int)NV3, 8, 6, 1,
        buf + O_X4P, buf + O_P4P, buf + O_CNT4, 0);
    pool_finalize_kernel<128><<<cdiv(NV4, 256), 256>>>(buf + O_X4P, buf + O_P4P,
        buf + O_CNT4, (int)NV4, 1);

    // ---------------- Layer 5: Cin=130 -> Cout=128, V=192, E=3072 ----------
    featcat_kernel<<<cdiv(NV4 * 130, 256), 256>>>(buf + O_X4P, 128, buf + O_P4P,
        buf + O_FC4, (int)NV4);
    edge_scatter_v4<130><<<scat_grid(NE4 * 260), 256>>>(e4, NE4, buf + O_P4P, buf + O_FC4,
                                                        buf + O_G5, buf + O_DEG5, 1.5f);
    spline_gemm_kernel<130, 128, 32><<<cdiv(NV4, 32), 256>>>(buf + O_G5, buf + O_DEG5,
        buf + O_FC4, W5, R5, b5, buf + O_H5, (int)NV4);
    cudaMemcpyAsync(out + NV3 * 128, buf + O_H5, NV4 * 128 * sizeof(float),
                    cudaMemcpyDeviceToDevice, 0);
}

// round 3
// speedup vs baseline: 1.8984x; 1.2182x over previous
#include <cuda_runtime.h>
#include <cuda_bf16.h>

// ---------------------------------------------------------------------------
// Problem constants
// ---------------------------------------------------------------------------
constexpr long NV0 = 300000, NV1 = 98304, NV2 = 12288, NV3 = 1536, NV4 = 192;
constexpr long NE0 = 3600000, NE1 = 786432, NE2 = 196608, NE3 = 24576, NE4 = 3072;

// ---------------------------------------------------------------------------
// Float scratch. Zero-region first (pool accumulators only).
// ---------------------------------------------------------------------------
constexpr long O_X1P = 0;
constexpr long O_X2P = O_X1P + NV1 * 16;
constexpr long O_X3P = O_X2P + NV2 * 64;
constexpr long O_X4P = O_X3P + NV3 * 128;
constexpr long O_P1P = O_X4P + NV4 * 128;
constexpr long O_P2P = O_P1P + NV1 * 3;
constexpr long O_P3P = O_P2P + NV2 * 3;
constexpr long O_P4P = O_P3P + NV3 * 3;
constexpr long O_CNT1 = O_P4P + NV4 * 3;
constexpr long O_CNT2 = O_CNT1 + NV1;
constexpr long O_CNT3 = O_CNT2 + NV2;
constexpr long O_CNT4 = O_CNT3 + NV3;
constexpr long ZERO_N = O_CNT4 + NV4;          // zeroed each run (multiple of 4)
// not zeroed:
constexpr long O_G2  = (ZERO_N + 3) & ~3L;
constexpr long O_G3  = O_G2 + NV1 * 144;
constexpr long O_G4  = O_G3 + NV2 * 528;
constexpr long O_G5  = O_G4 + NV3 * 1040;
constexpr long O_H1  = O_G5 + NV4 * 1040;
constexpr long O_FC1 = O_H1 + NV0 * 16;
constexpr long O_H2  = O_FC1 + NV1 * 18;
constexpr long O_FC2 = O_H2 + NV1 * 64;
constexpr long O_H3  = O_FC2 + NV2 * 66;
constexpr long O_FC3 = O_H3 + NV2 * 128;
constexpr long O_H4  = O_FC3 + NV3 * 130;
constexpr long O_FC4 = O_H4 + NV3 * 128;
constexpr long O_H5  = O_FC4 + NV4 * 130;
constexpr long TOTAL_N = O_H5 + NV4 * 128;

__device__ __align__(16) float g_buf[TOTAL_N];

// Int scratch for CSR (reused layer by layer, layers run sequentially)
constexpr long MAXV = 300000, MAXE = 3600000;
constexpr long I_CNT = 0;
constexpr long I_ROW = I_CNT + MAXV;
constexpr long I_CUR = I_ROW + MAXV;
constexpr long I_EBIN = I_CUR + MAXV;
constexpr long I_BS  = I_EBIN + MAXE;
constexpr long I_BO  = I_BS + 2048;
constexpr long TOTAL_I = I_BO + 2048;

__device__ __align__(16) int g_csr[TOTAL_I];

// ---------------------------------------------------------------------------
// Zero kernels
// ---------------------------------------------------------------------------
__global__ void zero_kernel(float* __restrict__ p, long n4) {
    float4* p4 = reinterpret_cast<float4*>(p);
    long i = (long)blockIdx.x * blockDim.x + threadIdx.x;
    long stride = (long)gridDim.x * blockDim.x;
    float4 z = make_float4(0.f, 0.f, 0.f, 0.f);
    for (; i < n4; i += stride) p4[i] = z;
}
__global__ void zeroi_kernel(int* __restrict__ p, int n) {
    int i = blockIdx.x * blockDim.x + threadIdx.x;
    if (i < n) p[i] = 0;
}

// ---------------------------------------------------------------------------
// CSR build: histogram -> exclusive scan -> bin
// ---------------------------------------------------------------------------
__global__ void hist_kernel(const int* __restrict__ dst, long E, int* __restrict__ cnt) {
    long i = (long)blockIdx.x * blockDim.x + threadIdx.x;
    long stride = (long)gridDim.x * blockDim.x;
    for (; i < E; i += stride) atomicAdd(&cnt[dst[i]], 1);
}

// 256 threads x 8 elems = 2048 per block. Writes exclusive scan + block sums.
__global__ void scan1_kernel(const int* __restrict__ in, int* __restrict__ out,
                             int* __restrict__ bsums, int n) {
    __shared__ int tot[256];
    int tid = threadIdx.x;
    long base = (long)blockIdx.x * 2048 + (long)tid * 8;
    int v[8]; int sum = 0;
    #pragma unroll
    for (int j = 0; j < 8; j++) { v[j] = (base + j < n) ? in[base + j] : 0; sum += v[j]; }
    tot[tid] = sum;
    __syncthreads();
    #pragma unroll
    for (int off = 1; off < 256; off <<= 1) {
        int t = (tid >= off) ? tot[tid - off] : 0;
        __syncthreads();
        tot[tid] += t;
        __syncthreads();
    }
    int run = (tid == 0) ? 0 : tot[tid - 1];
    #pragma unroll
    for (int j = 0; j < 8; j++) {
        if (base + j < n) out[base + j] = run;
        run += v[j];
    }
    if (bsums && tid == 255) bsums[blockIdx.x] = tot[255];
}

__global__ void scan_add_kernel(int* __restrict__ out, const int* __restrict__ boffs, int n) {
    int add = boffs[blockIdx.x];
    long base = (long)blockIdx.x * 2048 + (long)threadIdx.x * 8;
    #pragma unroll
    for (int j = 0; j < 8; j++)
        if (base + j < n) out[base + j] += add;
}

__global__ void bin_kernel(const int* __restrict__ dst, long E,
                           int* __restrict__ cursor, int* __restrict__ ebin) {
    long i = (long)blockIdx.x * blockDim.x + threadIdx.x;
    long stride = (long)gridDim.x * blockDim.x;
    for (; i < E; i += stride) {
        int p = atomicAdd(&cursor[dst[i]], 1);
        ebin[p] = (int)i;
    }
}

// ---------------------------------------------------------------------------
// Basis helper
// ---------------------------------------------------------------------------
__device__ __forceinline__ void basis8(float p0, float p1, float p2, float* b) {
    float q0 = 1.f - p0, q1 = 1.f - p1, q2 = 1.f - p2;
    float b00 = q0 * q1, b01 = p0 * q1, b10 = q0 * p1, b11 = p0 * p1;
    b[0] = b00 * q2; b[1] = b01 * q2; b[2] = b10 * q2; b[3] = b11 * q2;
    b[4] = b00 * p2; b[5] = b01 * p2; b[6] = b10 * p2; b[7] = b11 * p2;
}

// ---------------------------------------------------------------------------
// Layer 1 fully fused: gather + 24x16 GEMM + root + relu. Thread per node.
// feat_src = (x[src], pos_x[src], pos_y[src]); no featcat, no G buffer.
// ---------------------------------------------------------------------------
__global__ void __launch_bounds__(256)
spline1_fused_kernel(const int* __restrict__ rowptr, const int* __restrict__ cnt,
                     const int* __restrict__ ebin, const int* __restrict__ esrc,
                     const float* __restrict__ x, const float* __restrict__ pos,
                     const float* __restrict__ Wk,   // [24,16]
                     const float* __restrict__ Wr,   // [3,16]
                     const float* __restrict__ bias, // [16]
                     float* __restrict__ out, int V) {
    __shared__ float sWk[24][16];
    __shared__ float sWr[3][16];
    __shared__ float sb[16];
    int tid = threadIdx.x;
    for (int i = tid; i < 24 * 16; i += 256) sWk[i / 16][i % 16] = Wk[i];
    if (tid < 48) sWr[tid / 16][tid % 16] = Wr[tid];
    if (tid < 16) sb[tid] = bias[tid];
    __syncthreads();
    int v = blockIdx.x * 256 + tid;
    if (v >= V) return;

    float G[24];
    #pragma unroll
    for (int k = 0; k < 24; k++) G[k] = 0.f;

    float dx = pos[(long)v * 3 + 0];
    float dy = pos[(long)v * 3 + 1];
    float dz = pos[(long)v * 3 + 2];
    int start = rowptr[v];
    int deg = cnt[v];
    for (int j = 0; j < deg; j++) {
        int eid = ebin[start + j];
        int s = esrc[eid];
        float sx = pos[(long)s * 3 + 0];
        float sy = pos[(long)s * 3 + 1];
        float sz = pos[(long)s * 3 + 2];
        float p0 = __saturatef((dx - sx) * 20.0f + 0.5f);
        float p1 = __saturatef((dy - sy) * 20.0f + 0.5f);
        float p2 = __saturatef((dz - sz) * 20.0f + 0.5f);
        float b[8]; basis8(p0, p1, p2, b);
        float f0 = x[s], f1 = sx, f2 = sy;
        #pragma unroll
        for (int s8 = 0; s8 < 8; s8++) {
            G[s8 * 3 + 0] += b[s8] * f0;
            G[s8 * 3 + 1] += b[s8] * f1;
            G[s8 * 3 + 2] += b[s8] * f2;
        }
    }

    float acc[16];
    #pragma unroll
    for (int c = 0; c < 16; c++) acc[c] = 0.f;
    #pragma unroll
    for (int k = 0; k < 24; k++) {
        float g = G[k];
        #pragma unroll
        for (int c = 0; c < 16; c++) acc[c] += g * sWk[k][c];
    }
    float inv = 1.f / fmaxf((float)deg, 1.f);
    float f0 = x[v];
    float4* o4 = reinterpret_cast<float4*>(out + (long)v * 16);
    #pragma unroll
    for (int jj = 0; jj < 4; jj++) {
        float4 o;
        float* op = &o.x;
        #pragma unroll
        for (int u = 0; u < 4; u++) {
            int c = jj * 4 + u;
            float val = acc[c] * inv + f0 * sWr[0][c] + dx * sWr[1][c]
                      + dy * sWr[2][c] + sb[c];
            op[u] = fmaxf(val, 0.f);
        }
        o4[jj] = o;
    }
}

// ---------------------------------------------------------------------------
// Gather G rows for layers 2..5 (warp per node, no atomics, writes full rows).
// Lane l owns feature columns l, l+32, ... ; accumulates 8 spline corners.
// ---------------------------------------------------------------------------
template <int CIN>
__global__ void __launch_bounds__(256)
gather_G_kernel(const int* __restrict__ rowptr, const int* __restrict__ cnt,
                const int* __restrict__ ebin, const int* __restrict__ esrc,
                const float* __restrict__ pos, const float* __restrict__ feat,
                float* __restrict__ G, int V, float inv2mv) {
    constexpr int NJ = (CIN + 31) / 32;
    int lane = threadIdx.x & 31;
    int w = blockIdx.x * 8 + (threadIdx.x >> 5);
    if (w >= V) return;
    int v = w;
    float dx = pos[(long)v * 3 + 0];
    float dy = pos[(long)v * 3 + 1];
    float dz = pos[(long)v * 3 + 2];
    float Gacc[NJ][8];
    #pragma unroll
    for (int jj = 0; jj < NJ; jj++)
        #pragma unroll
        for (int s8 = 0; s8 < 8; s8++) Gacc[jj][s8] = 0.f;

    int start = rowptr[v];
    int deg = cnt[v];
    for (int j = 0; j < deg; j++) {
        int eid = ebin[start + j];           // lane-uniform -> broadcast
        int s = esrc[eid];
        float sx = pos[(long)s * 3 + 0];
        float sy = pos[(long)s * 3 + 1];
        float sz = pos[(long)s * 3 + 2];
        float p0 = __saturatef((dx - sx) * inv2mv + 0.5f);
        float p1 = __saturatef((dy - sy) * inv2mv + 0.5f);
        float p2 = __saturatef((dz - sz) * inv2mv + 0.5f);
        float b[8]; basis8(p0, p1, p2, b);
        float f[NJ];
        #pragma unroll
        for (int jj = 0; jj < NJ; jj++) {
            int idx = lane + jj * 32;
            f[jj] = (idx < CIN) ? feat[(long)s * CIN + idx] : 0.f;
        }
        #pragma unroll
        for (int s8 = 0; s8 < 8; s8++)
            #pragma unroll
            for (int jj = 0; jj < NJ; jj++) Gacc[jj][s8] += b[s8] * f[jj];
    }
    #pragma unroll
    for (int s8 = 0; s8 < 8; s8++)
        #pragma unroll
        for (int jj = 0; jj < NJ; jj++) {
            int idx = lane + jj * 32;
            if (idx < CIN) G[(long)v * (8 * CIN) + s8 * CIN + idx] = Gacc[jj][s8];
        }
}

// ---------------------------------------------------------------------------
// featcat: fc[v, 0..Ch-1] = h, fc[v, Ch..Ch+1] = pos.xy
// ---------------------------------------------------------------------------
__global__ void featcat_kernel(const float* __restrict__ h, int Ch,
                               const float* __restrict__ pos,
                               float* __restrict__ fc, int V) {
    int Cin = Ch + 2;
    long total = (long)V * Cin;
    long idx = (long)blockIdx.x * blockDim.x + threadIdx.x;
    if (idx >= total) return;
    int v = (int)(idx / Cin);
    int i = (int)(idx - (long)v * Cin);
    fc[idx] = (i < Ch) ? h[(long)v * Ch + i] : pos[(long)v * 3 + (i - Ch)];
}

// ---------------------------------------------------------------------------
// Register-tiled GEMM for layers 2..5 (deg now int from CSR counts).
// ---------------------------------------------------------------------------
template <int CIN, int COUT, int TV>
__global__ void __launch_bounds__(256)
spline_gemm_kernel(const float* __restrict__ G, const int* __restrict__ deg,
                   const float* __restrict__ feat,
                   const float* __restrict__ Wk,   // [8*CIN, COUT]
                   const float* __restrict__ Wr,   // [CIN, COUT]
                   const float* __restrict__ bias, // [COUT]
                   float* __restrict__ out, int V) {
    constexpr int K1 = 8 * CIN;
    constexpr int NR = TV / 16;
    constexpr int NC = COUT / 16;
    __shared__ float Gs[32][TV + 1];
    __shared__ float Ws[32][COUT];
    int tid = threadIdx.x;
    int tx = tid & 15, ty = tid >> 4;
    int v0 = blockIdx.x * TV;
    float acc1[NR][NC];
    float acc2[NR][NC];
    #pragma unroll
    for (int r = 0; r < NR; r++)
        #pragma unroll
        for (int c = 0; c < NC; c++) { acc1[r][c] = 0.f; acc2[r][c] = 0.f; }

    for (int k0 = 0; k0 < K1; k0 += 32) {
        #pragma unroll
        for (int j = 0; j < TV * 32 / 256; j++) {
            int idx = tid + j * 256;
            int r = idx >> 5, kk = idx & 31;
            int v = v0 + r, k = k0 + kk;
            Gs[kk][r] = (v < V && k < K1) ? G[(long)v * K1 + k] : 0.f;
        }
        #pragma unroll
        for (int j = 0; j < 32 * COUT / 256; j++) {
            int idx = tid + j * 256;
            int kk = idx / COUT, cc = idx - kk * COUT;
            int k = k0 + kk;
            Ws[kk][cc] = (k < K1) ? Wk[(long)k * COUT + cc] : 0.f;
        }
        __syncthreads();
        #pragma unroll
        for (int kk = 0; kk < 32; kk++) {
            float a[NR], b[NC];
            #pragma unroll
            for (int r = 0; r < NR; r++) a[r] = Gs[kk][ty + r * 16];
            #pragma unroll
            for (int c = 0; c < NC; c++) b[c] = Ws[kk][tx + c * 16];
            #pragma unroll
            for (int r = 0; r < NR; r++)
                #pragma unroll
                for (int c = 0; c < NC; c++) acc1[r][c] += a[r] * b[c];
        }
        __syncthreads();
    }

    for (int k0 = 0; k0 < CIN; k0 += 32) {
        #pragma unroll
        for (int j = 0; j < TV * 32 / 256; j++) {
            int idx = tid + j * 256;
            int r = idx >> 5, kk = idx & 31;
            int v = v0 + r, k = k0 + kk;
            Gs[kk][r] = (v < V && k < CIN) ? feat[(long)v * CIN + k] : 0.f;
        }
        #pragma unroll
        for (int j = 0; j < 32 * COUT / 256; j++) {
            int idx = tid + j * 256;
            int kk = idx / COUT, cc = idx - kk * COUT;
            int k = k0 + kk;
            Ws[kk][cc] = (k < CIN) ? Wr[(long)k * COUT + cc] : 0.f;
        }
        __syncthreads();
        #pragma unroll
        for (int kk = 0; kk < 32; kk++) {
            float a[NR], b[NC];
            #pragma unroll
            for (int r = 0; r < NR; r++) a[r] = Gs[kk][ty + r * 16];
            #pragma unroll
            for (int c = 0; c < NC; c++) b[c] = Ws[kk][tx + c * 16];
            #pragma unroll
            for (int r = 0; r < NR; r++)
                #pragma unroll
                for (int c = 0; c < NC; c++) acc2[r][c] += a[r] * b[c];
        }
        __syncthreads();
    }

    #pragma unroll
    for (int r = 0; r < NR; r++) {
        int v = v0 + ty + r * 16;
        if (v < V) {
            float inv = 1.f / fmaxf((float)deg[v], 1.f);
            #pragma unroll
            for (int c = 0; c < NC; c++) {
                int col = tx + c * 16;
                float o = acc1[r][c] * inv + acc2[r][c] + bias[col];
                out[(long)v * COUT + col] = fmaxf(o, 0.f);
            }
        }
    }
}

// ---------------------------------------------------------------------------
// Voxel pooling (unchanged: warp per node, atomicMax/Add on zeroed buffers)
// ---------------------------------------------------------------------------
template <int C>
__global__ void __launch_bounds__(256)
pool_scatter_kernel(const float* __restrict__ h, const float* __restrict__ pos,
                    const int* __restrict__ batch, int cellsPrev,
                    int V_in, int nx, int ny, int nt,
                    float* __restrict__ xp, float* __restrict__ posSum,
                    float* __restrict__ cnt, int isMax) {
    int lane = threadIdx.x & 31;
    long w = (long)blockIdx.x * (blockDim.x >> 5) + (threadIdx.x >> 5);
    if (w >= V_in) return;
    int v = (int)w;
    int b = batch ? batch[v] : v / cellsPrev;
    float px = pos[(long)v * 3 + 0];
    float py = pos[(long)v * 3 + 1];
    float pt = pos[(long)v * 3 + 2];
    int ix = min(max((int)floorf(px * nx), 0), nx - 1);
    int iy = min(max((int)floorf(py * ny), 0), ny - 1);
    int it = min(max((int)floorf(pt * nt), 0), nt - 1);
    long cl = (((long)b * nx + ix) * ny + iy) * nt + it;
    for (int k = lane; k < C; k += 32) {
        float val = h[(long)v * C + k];
        if (isMax)
            atomicMax((int*)(xp + cl * C + k), __float_as_int(val));
        else
            atomicAdd(xp + cl * C + k, val);
    }
    if (lane < 3) atomicAdd(posSum + cl * 3 + lane, pos[(long)v * 3 + lane]);
    if (lane == 0) atomicAdd(cnt + cl, 1.0f);
}

template <int C>
__global__ void pool_finalize_kernel(float* __restrict__ xp, float* __restrict__ posSum,
                                     const float* __restrict__ cnt, int V, int isMean) {
    int v = blockIdx.x * blockDim.x + threadIdx.x;
    if (v >= V) return;
    float cn = fmaxf(cnt[v], 1.0f);
    float inv = 1.0f / cn;
    posSum[(long)v * 3 + 0] *= inv;
    posSum[(long)v * 3 + 1] *= inv;
    posSum[(long)v * 3 + 2] *= inv;
    if (isMean) {
        for (int k = 0; k < C; k++) xp[(long)v * C + k] *= inv;
    }
}

// ---------------------------------------------------------------------------
// Launch
// ---------------------------------------------------------------------------
static inline int cdiv(long a, long b) { return (int)((a + b - 1) / b); }

static void build_csr(const int* e, long E, int V, int* ip) {
    int* cnt = ip + I_CNT;
    int* row = ip + I_ROW;
    int* cur = ip + I_CUR;
    int* ebin = ip + I_EBIN;
    int* bs = ip + I_BS;
    int* bo = ip + I_BO;
    const int* dst = e + E;
    int nb = cdiv(V, 2048);
    zeroi_kernel<<<cdiv(V, 256), 256>>>(cnt, V);
    hist_kernel<<<cdiv(E, 256) > 4096 ? 4096 : cdiv(E, 256), 256>>>(dst, E, cnt);
    scan1_kernel<<<nb, 256>>>(cnt, row, bs, V);
    scan1_kernel<<<1, 256>>>(bs, bo, nullptr, nb);
    scan_add_kernel<<<nb, 256>>>(row, bo, V);
    cudaMemcpyAsync(cur, row, (size_t)V * sizeof(int), cudaMemcpyDeviceToDevice, 0);
    bin_kernel<<<cdiv(E, 256) > 4096 ? 4096 : cdiv(E, 256), 256>>>(dst, E, cur, ebin);
}

extern "C" void kernel_launch(void* const* d_in, const int* in_sizes, int n_in,
                              void* d_out, int out_size) {
    const float* x    = (const float*)d_in[0];
    const float* pos0 = (const float*)d_in[1];
    const int*   batch = (const int*)d_in[2];
    const int* e0 = (const int*)d_in[3];
    const int* e1 = (const int*)d_in[4];
    const int* e2 = (const int*)d_in[5];
    const int* e3 = (const int*)d_in[6];
    const int* e4 = (const int*)d_in[7];
    const float* W1 = (const float*)d_in[8];
    const float* R1 = (const float*)d_in[9];
    const float* b1 = (const float*)d_in[10];
    const float* W2 = (const float*)d_in[11];
    const float* R2 = (const float*)d_in[12];
    const float* b2 = (const float*)d_in[13];
    const float* W3 = (const float*)d_in[14];
    const float* R3 = (const float*)d_in[15];
    const float* b3 = (const float*)d_in[16];
    const float* W4 = (const float*)d_in[17];
    const float* R4 = (const float*)d_in[18];
    const float* b4 = (const float*)d_in[19];
    const float* W5 = (const float*)d_in[20];
    const float* R5 = (const float*)d_in[21];
    const float* b5 = (const float*)d_in[22];
    float* out = (float*)d_out;

    float* buf;
    cudaGetSymbolAddress((void**)&buf, g_buf);
    int* ip;
    cudaGetSymbolAddress((void**)&ip, g_csr);
    int* row = ip + I_ROW;
    int* cnt = ip + I_CNT;
    int* ebin = ip + I_EBIN;

    // Zero pool accumulators
    zero_kernel<<<512, 256>>>(buf, ZERO_N / 4);

    // ---------------- Layer 1: Cin=3 -> Cout=16, V=300000, E=3.6M ----------
    build_csr(e0, NE0, (int)NV0, ip);
    spline1_fused_kernel<<<cdiv(NV0, 256), 256>>>(row, cnt, ebin, e0,
        x, pos0, W1, R1, b1, buf + O_H1, (int)NV0);
    pool_scatter_kernel<16><<<cdiv(NV0, 8), 256>>>(buf + O_H1, pos0, batch, 0,
        (int)NV0, 64, 48, 8, buf + O_X1P, buf + O_P1P, buf + O_CNT1, 1);
    pool_finalize_kernel<16><<<cdiv(NV1, 256), 256>>>(buf + O_X1P, buf + O_P1P,
        buf + O_CNT1, (int)NV1, 0);

    // ---------------- Layer 2: Cin=18 -> Cout=64, V=98304, E=786432 --------
    featcat_kernel<<<cdiv(NV1 * 18, 256), 256>>>(buf + O_X1P, 16, buf + O_P1P,
        buf + O_FC1, (int)NV1);
    build_csr(e1, NE1, (int)NV1, ip);
    gather_G_kernel<18><<<cdiv(NV1, 8), 256>>>(row, cnt, ebin, e1,
        buf + O_P1P, buf + O_FC1, buf + O_G2, (int)NV1, 10.0f);
    spline_gemm_kernel<18, 64, 64><<<cdiv(NV1, 64), 256>>>(buf + O_G2, cnt,
        buf + O_FC1, W2, R2, b2, buf + O_H2, (int)NV1);
    pool_scatter_kernel<64><<<cdiv(NV1, 8), 256>>>(buf + O_H2, buf + O_P1P,
        (const int*)nullptr, 64 * 48 * 8, (int)NV1, 32, 24, 4,
        buf + O_X2P, buf + O_P2P, buf + O_CNT2, 1);
    pool_finalize_kernel<64><<<cdiv(NV2, 256), 256>>>(buf + O_X2P, buf + O_P2P,
        buf + O_CNT2, (int)NV2, 0);

    // ---------------- Layer 3: Cin=66 -> Cout=128, V=12288, E=196608 -------
    featcat_kernel<<<cdiv(NV2 * 66, 256), 256>>>(buf + O_X2P, 64, buf + O_P2P,
        buf + O_FC2, (int)NV2);
    build_csr(e2, NE2, (int)NV2, ip);
    gather_G_kernel<66><<<cdiv(NV2, 8), 256>>>(row, cnt, ebin, e2,
        buf + O_P2P, buf + O_FC2, buf + O_G3, (int)NV2, 6.0f);
    spline_gemm_kernel<66, 128, 64><<<cdiv(NV2, 64), 256>>>(buf + O_G3, cnt,
        buf + O_FC2, W3, R3, b3, buf + O_H3, (int)NV2);
    pool_scatter_kernel<128><<<cdiv(NV2, 8), 256>>>(buf + O_H3, buf + O_P2P,
        (const int*)nullptr, 32 * 24 * 4, (int)NV2, 16, 12, 2,
        buf + O_X3P, buf + O_P3P, buf + O_CNT3, 1);
    pool_finalize_kernel<128><<<cdiv(NV3, 256), 256>>>(buf + O_X3P, buf + O_P3P,
        buf + O_CNT3, (int)NV3, 0);

    // ---------------- Layer 4: Cin=130 -> Cout=128, V=1536, E=24576 --------
    featcat_kernel<<<cdiv(NV3 * 130, 256), 256>>>(buf + O_X3P, 128, buf + O_P3P,
        buf + O_FC3, (int)NV3);
    build_csr(e3, NE3, (int)NV3, ip);
    gather_G_kernel<130><<<cdiv(NV3, 8), 256>>>(row, cnt, ebin, e3,
        buf + O_P3P, buf + O_FC3, buf + O_G4, (int)NV3, 3.0f);
    spline_gemm_kernel<130, 128, 32><<<cdiv(NV3, 32), 256>>>(buf + O_G4, cnt,
        buf + O_FC3, W4, R4, b4, buf + O_H4, (int)NV3);
    cudaMemcpyAsync(out, buf + O_H4, NV3 * 128 * sizeof(float),
                    cudaMemcpyDeviceToDevice, 0);
    pool_scatter_kernel<128><<<cdiv(NV3, 8), 256>>>(buf + O_H4, buf + O_P3P,
        (const int*)nullptr, 16 * 12 * 2, (int)NV3, 8, 6, 1,
        buf + O_X4P, buf + O_P4P, buf + O_CNT4, 0);
    pool_finalize_kernel<128><<<cdiv(NV4, 256), 256>>>(buf + O_X4P, buf + O_P4P,
        buf + O_CNT4, (int)NV4, 1);

    // ---------------- Layer 5: Cin=130 -> Cout=128, V=192, E=3072 ----------
    featcat_kernel<<<cdiv(NV4 * 130, 256), 256>>>(buf + O_X4P, 128, buf + O_P4P,
        buf + O_FC4, (int)NV4);
    build_csr(e4, NE4, (int)NV4, ip);
    gather_G_kernel<130><<<cdiv(NV4, 8), 256>>>(row, cnt, ebin, e4,
        buf + O_P4P, buf + O_FC4, buf + O_G5, (int)NV4, 1.5f);
    spline_gemm_kernel<130, 128, 32><<<cdiv(NV4, 32), 256>>>(buf + O_G5, cnt,
        buf + O_FC4, W5, R5, b5, buf + O_H5, (int)NV4);
    cudaMemcpyAsync(out + NV3 * 128, buf + O_H5, NV4 * 128 * sizeof(float),
                    cudaMemcpyDeviceToDevice, 0);
}

// round 4
// speedup vs baseline: 2.3066x; 1.2150x over previous
#include <cuda_runtime.h>
#include <cuda_bf16.h>

// ---------------------------------------------------------------------------
// Problem constants
// ---------------------------------------------------------------------------
constexpr long NV0 = 300000, NV1 = 98304, NV2 = 12288, NV3 = 1536, NV4 = 192;
constexpr long NE0 = 3600000, NE1 = 786432, NE2 = 196608, NE3 = 24576, NE4 = 3072;
constexpr long TOTV = NV0 + NV1 + NV2 + NV3 + NV4;     // 412320
constexpr long TOTE = NE0 + NE1 + NE2 + NE3 + NE4;     // 4610688

// ---------------------------------------------------------------------------
// Float scratch. Zero-region first: fc (pool targets) + posSum + pool counts.
// ---------------------------------------------------------------------------
constexpr long O_FC1 = 0;                      // [NV1, 18]
constexpr long O_FC2 = O_FC1 + NV1 * 18;       // [NV2, 66]
constexpr long O_FC3 = O_FC2 + NV2 * 66;       // [NV3, 130]
constexpr long O_FC4 = O_FC3 + NV3 * 130;      // [NV4, 130]
constexpr long O_P1P = O_FC4 + NV4 * 130;
constexpr long O_P2P = O_P1P + NV1 * 3;
constexpr long O_P3P = O_P2P + NV2 * 3;
constexpr long O_P4P = O_P3P + NV3 * 3;
constexpr long O_CNT1 = O_P4P + NV4 * 3;
constexpr long O_CNT2 = O_CNT1 + NV1;
constexpr long O_CNT3 = O_CNT2 + NV2;
constexpr long O_CNT4 = O_CNT3 + NV3;
constexpr long ZERO_N = O_CNT4 + NV4;          // zeroed each run
// not zeroed:
constexpr long O_PXA = (ZERO_N + 3) & ~3L;     // [NV0] float4
constexpr long O_G2  = O_PXA + NV0 * 4;
constexpr long O_G3  = O_G2 + NV1 * 144;
constexpr long O_G4  = O_G3 + NV2 * 528;
constexpr long O_G5  = O_G4 + NV3 * 1040;
constexpr long TOTAL_N = O_G5 + NV4 * 1040;

__device__ __align__(16) float g_buf[TOTAL_N];

// Int scratch: concatenated CSR over all 5 layers.
constexpr long I_CNT = 0;
constexpr long I_ROW = I_CNT + TOTV;
constexpr long I_CUR = I_ROW + TOTV;
constexpr long I_EBIN = I_CUR + TOTV;
constexpr long I_BS  = I_EBIN + TOTE;
constexpr long I_BO  = I_BS + 2048;
constexpr long TOTAL_I = I_BO + 2048;

__device__ __align__(16) int g_csr[TOTAL_I];

// Per-layer node offsets into the concatenated cnt/row arrays
constexpr int VOFF0 = 0;
constexpr int VOFF1 = (int)NV0;
constexpr int VOFF2 = (int)(NV0 + NV1);
constexpr int VOFF3 = (int)(NV0 + NV1 + NV2);
constexpr int VOFF4 = (int)(NV0 + NV1 + NV2 + NV3);

struct Batch5 {
    const int* e[5];
    long E[5];
    int voff[5];
};

// ---------------------------------------------------------------------------
// Zero kernels
// ---------------------------------------------------------------------------
__global__ void zero_kernel(float* __restrict__ p, long n4) {
    float4* p4 = reinterpret_cast<float4*>(p);
    long i = (long)blockIdx.x * blockDim.x + threadIdx.x;
    long stride = (long)gridDim.x * blockDim.x;
    float4 z = make_float4(0.f, 0.f, 0.f, 0.f);
    for (; i < n4; i += stride) p4[i] = z;
}
__global__ void zeroi_kernel(int* __restrict__ p, long n) {
    long i = (long)blockIdx.x * blockDim.x + threadIdx.x;
    if (i < n) p[i] = 0;
}

// ---------------------------------------------------------------------------
// pxa prep: pxa[v] = (pos.x, pos.y, pos.z, x[v])
// ---------------------------------------------------------------------------
__global__ void pxa_kernel(const float* __restrict__ pos, const float* __restrict__ x,
                           float4* __restrict__ pxa, int V) {
    int v = blockIdx.x * blockDim.x + threadIdx.x;
    if (v >= V) return;
    pxa[v] = make_float4(pos[(long)v * 3], pos[(long)v * 3 + 1], pos[(long)v * 3 + 2], x[v]);
}

// ---------------------------------------------------------------------------
// Batched CSR build: one hist + one scan (3 kernels) + one bin for all layers.
// ebin stores the SRC NODE ID (not the edge id) -> one less indirection.
// ---------------------------------------------------------------------------
__global__ void hist5_kernel(Batch5 p, int* __restrict__ cnt) {
    int L = blockIdx.y;
    const int* dst = p.e[L] + p.E[L];
    int* c = cnt + p.voff[L];
    long i = (long)blockIdx.x * blockDim.x + threadIdx.x;
    long stride = (long)gridDim.x * blockDim.x;
    long E = p.E[L];
    for (; i < E; i += stride) atomicAdd(&c[dst[i]], 1);
}

__global__ void scan1_kernel(const int* __restrict__ in, int* __restrict__ out,
                             int* __restrict__ bsums, int n) {
    __shared__ int tot[256];
    int tid = threadIdx.x;
    long base = (long)blockIdx.x * 2048 + (long)tid * 8;
    int v[8]; int sum = 0;
    #pragma unroll
    for (int j = 0; j < 8; j++) { v[j] = (base + j < n) ? in[base + j] : 0; sum += v[j]; }
    tot[tid] = sum;
    __syncthreads();
    #pragma unroll
    for (int off = 1; off < 256; off <<= 1) {
        int t = (tid >= off) ? tot[tid - off] : 0;
        __syncthreads();
        tot[tid] += t;
        __syncthreads();
    }
    int run = (tid == 0) ? 0 : tot[tid - 1];
    #pragma unroll
    for (int j = 0; j < 8; j++) {
        if (base + j < n) out[base + j] = run;
        run += v[j];
    }
    if (bsums && tid == 255) bsums[blockIdx.x] = tot[255];
}

__global__ void scan_add_kernel(int* __restrict__ out, const int* __restrict__ boffs, int n) {
    int add = boffs[blockIdx.x];
    long base = (long)blockIdx.x * 2048 + (long)threadIdx.x * 8;
    #pragma unroll
    for (int j = 0; j < 8; j++)
        if (base + j < n) out[base + j] += add;
}

__global__ void bin5_kernel(Batch5 p, int* __restrict__ cur, int* __restrict__ ebin) {
    int L = blockIdx.y;
    const int* src = p.e[L];
    const int* dst = src + p.E[L];
    int* cu = cur + p.voff[L];
    long i = (long)blockIdx.x * blockDim.x + threadIdx.x;
    long stride = (long)gridDim.x * blockDim.x;
    long E = p.E[L];
    for (; i < E; i += stride) {
        int pp = atomicAdd(&cu[dst[i]], 1);   // global position into ebin
        ebin[pp] = src[i];
    }
}

// ---------------------------------------------------------------------------
// Basis helper
// ---------------------------------------------------------------------------
__device__ __forceinline__ void basis8(float p0, float p1, float p2, float* b) {
    float q0 = 1.f - p0, q1 = 1.f - p1, q2 = 1.f - p2;
    float b00 = q0 * q1, b01 = p0 * q1, b10 = q0 * p1, b11 = p0 * p1;
    b[0] = b00 * q2; b[1] = b01 * q2; b[2] = b10 * q2; b[3] = b11 * q2;
    b[4] = b00 * p2; b[5] = b01 * p2; b[6] = b10 * p2; b[7] = b11 * p2;
}

// ---------------------------------------------------------------------------
// Layer 1 fully fused: gather + 24x16 GEMM + root + relu + MAX-POOL into fc1.
// Thread per node. One float4 random load per edge (pxa).
// ---------------------------------------------------------------------------
__global__ void __launch_bounds__(256)
spline1_fused_kernel(const int* __restrict__ rowptr, const int* __restrict__ cnt,
                     const int* __restrict__ ebin,
                     const float4* __restrict__ pxa, const int* __restrict__ batch,
                     const float* __restrict__ Wk,   // [24,16]
                     const float* __restrict__ Wr,   // [3,16]
                     const float* __restrict__ bias, // [16]
                     float* __restrict__ fc1,        // [NV1,18] zeroed
                     float* __restrict__ posSum,     // [NV1,3]
                     float* __restrict__ cntPool,    // [NV1]
                     int V) {
    __shared__ float sWk[24][16];
    __shared__ float sWr[3][16];
    __shared__ float sb[16];
    int tid = threadIdx.x;
    for (int i = tid; i < 24 * 16; i += 256) sWk[i / 16][i % 16] = Wk[i];
    if (tid < 48) sWr[tid / 16][tid % 16] = Wr[tid];
    if (tid < 16) sb[tid] = bias[tid];
    __syncthreads();
    int v = blockIdx.x * 256 + tid;
    if (v >= V) return;

    float G[24];
    #pragma unroll
    for (int k = 0; k < 24; k++) G[k] = 0.f;

    float4 me = pxa[v];
    float dx = me.x, dy = me.y, dz = me.z;
    int start = rowptr[v];
    int deg = cnt[v];
    #pragma unroll 2
    for (int j = 0; j < deg; j++) {
        int s = ebin[start + j];
        float4 sp = pxa[s];
        float p0 = __saturatef((dx - sp.x) * 20.0f + 0.5f);
        float p1 = __saturatef((dy - sp.y) * 20.0f + 0.5f);
        float p2 = __saturatef((dz - sp.z) * 20.0f + 0.5f);
        float b[8]; basis8(p0, p1, p2, b);
        #pragma unroll
        for (int s8 = 0; s8 < 8; s8++) {
            G[s8 * 3 + 0] += b[s8] * sp.w;
            G[s8 * 3 + 1] += b[s8] * sp.x;
            G[s8 * 3 + 2] += b[s8] * sp.y;
        }
    }

    float acc[16];
    #pragma unroll
    for (int c = 0; c < 16; c++) acc[c] = 0.f;
    #pragma unroll
    for (int k = 0; k < 24; k++) {
        float g = G[k];
        #pragma unroll
        for (int c = 0; c < 16; c++) acc[c] += g * sWk[k][c];
    }
    float inv = 1.f / fmaxf((float)deg, 1.f);

    // cluster for pooling into grid (64,48,8)
    int b_ = batch[v];
    int ix = min(max((int)floorf(dx * 64.f), 0), 63);
    int iy = min(max((int)floorf(dy * 48.f), 0), 47);
    int it = min(max((int)floorf(dz * 8.f), 0), 7);
    long cl = (((long)b_ * 64 + ix) * 48 + iy) * 8 + it;
    float* fcrow = fc1 + cl * 18;

    #pragma unroll
    for (int c = 0; c < 16; c++) {
        float val = acc[c] * inv + me.w * sWr[0][c] + dx * sWr[1][c]
                  + dy * sWr[2][c] + sb[c];
        val = fmaxf(val, 0.f);
        atomicMax((int*)(fcrow + c), __float_as_int(val));
    }
    atomicAdd(posSum + cl * 3 + 0, dx);
    atomicAdd(posSum + cl * 3 + 1, dy);
    atomicAdd(posSum + cl * 3 + 2, dz);
    atomicAdd(cntPool + cl, 1.0f);
}

// ---------------------------------------------------------------------------
// finalize: posp = posSum / max(cnt,1); fc[:, C..C+1] = posp.xy;
// optional mean-scale of first C cols.
// ---------------------------------------------------------------------------
template <int C>
__global__ void finalize_kernel(float* __restrict__ fc, float* __restrict__ posSum,
                                const float* __restrict__ cnt, int V, int isMean) {
    int v = blockIdx.x * blockDim.x + threadIdx.x;
    if (v >= V) return;
    float cn = fmaxf(cnt[v], 1.0f);
    float inv = 1.0f / cn;
    float px = posSum[(long)v * 3 + 0] * inv;
    float py = posSum[(long)v * 3 + 1] * inv;
    float pz = posSum[(long)v * 3 + 2] * inv;
    posSum[(long)v * 3 + 0] = px;
    posSum[(long)v * 3 + 1] = py;
    posSum[(long)v * 3 + 2] = pz;
    float* row = fc + (long)v * (C + 2);
    row[C] = px;
    row[C + 1] = py;
    if (isMean)
        for (int k = 0; k < C; k++) row[k] *= inv;
}

// ---------------------------------------------------------------------------
// Gather G rows for layers 2..5 (warp per node, ebin holds src ids).
// ---------------------------------------------------------------------------
template <int CIN>
__global__ void __launch_bounds__(256)
gather_G_kernel(const int* __restrict__ rowptr, const int* __restrict__ cnt,
                const int* __restrict__ ebin,
                const float* __restrict__ pos, const float* __restrict__ feat,
                float* __restrict__ G, int V, float inv2mv) {
    constexpr int NJ = (CIN + 31) / 32;
    int lane = threadIdx.x & 31;
    int v = blockIdx.x * 8 + (threadIdx.x >> 5);
    if (v >= V) return;
    float dx = pos[(long)v * 3 + 0];
    float dy = pos[(long)v * 3 + 1];
    float dz = pos[(long)v * 3 + 2];
    float Gacc[NJ][8];
    #pragma unroll
    for (int jj = 0; jj < NJ; jj++)
        #pragma unroll
        for (int s8 = 0; s8 < 8; s8++) Gacc[jj][s8] = 0.f;

    int start = rowptr[v];
    int deg = cnt[v];
    for (int j = 0; j < deg; j++) {
        int s = ebin[start + j];             // lane-uniform -> broadcast
        float sx = pos[(long)s * 3 + 0];
        float sy = pos[(long)s * 3 + 1];
        float sz = pos[(long)s * 3 + 2];
        float p0 = __saturatef((dx - sx) * inv2mv + 0.5f);
        float p1 = __saturatef((dy - sy) * inv2mv + 0.5f);
        float p2 = __saturatef((dz - sz) * inv2mv + 0.5f);
        float b[8]; basis8(p0, p1, p2, b);
        float f[NJ];
        #pragma unroll
        for (int jj = 0; jj < NJ; jj++) {
            int idx = lane + jj * 32;
            f[jj] = (idx < CIN) ? feat[(long)s * CIN + idx] : 0.f;
        }
        #pragma unroll
        for (int s8 = 0; s8 < 8; s8++)
            #pragma unroll
            for (int jj = 0; jj < NJ; jj++) Gacc[jj][s8] += b[s8] * f[jj];
    }
    #pragma unroll
    for (int s8 = 0; s8 < 8; s8++)
        #pragma unroll
        for (int jj = 0; jj < NJ; jj++) {
            int idx = lane + jj * 32;
            if (idx < CIN) G[(long)v * (8 * CIN) + s8 * CIN + idx] = Gacc[jj][s8];
        }
}

// ---------------------------------------------------------------------------
// Register-tiled GEMM, fused epilogue: relu output, optional write to `out`,
// optional max/mean pooling directly into next layer's fc (zero-initialized).
// POOL: 0 none, 1 max, 2 mean.
// ---------------------------------------------------------------------------
template <int CIN, int COUT, int TV, int POOL, bool WOUT>
__global__ void __launch_bounds__(256)
spline_gemm_kernel(const float* __restrict__ G, const int* __restrict__ deg,
                   const float* __restrict__ feat,
                   const float* __restrict__ Wk,   // [8*CIN, COUT]
                   const float* __restrict__ Wr,   // [CIN, COUT]
                   const float* __restrict__ bias, // [COUT]
                   float* __restrict__ out, int V,
                   // pooling params
                   const float* __restrict__ pos, int cellsPrev,
                   int nx, int ny, int nt,
                   float* __restrict__ fcN, float* __restrict__ posSum,
                   float* __restrict__ cntPool) {
    constexpr int K1 = 8 * CIN;
    constexpr int NR = TV / 16;
    constexpr int NC = COUT / 16;
    __shared__ float Gs[32][TV + 1];
    __shared__ float Ws[32][COUT];
    int tid = threadIdx.x;
    int tx = tid & 15, ty = tid >> 4;
    int v0 = blockIdx.x * TV;
    float acc1[NR][NC];
    float acc2[NR][NC];
    #pragma unroll
    for (int r = 0; r < NR; r++)
        #pragma unroll
        for (int c = 0; c < NC; c++) { acc1[r][c] = 0.f; acc2[r][c] = 0.f; }

    for (int k0 = 0; k0 < K1; k0 += 32) {
        #pragma unroll
        for (int j = 0; j < TV * 32 / 256; j++) {
            int idx = tid + j * 256;
            int r = idx >> 5, kk = idx & 31;
            int v = v0 + r, k = k0 + kk;
            Gs[kk][r] = (v < V && k < K1) ? G[(long)v * K1 + k] : 0.f;
        }
        #pragma unroll
        for (int j = 0; j < 32 * COUT / 256; j++) {
            int idx = tid + j * 256;
            int kk = idx / COUT, cc = idx - kk * COUT;
            int k = k0 + kk;
            Ws[kk][cc] = (k < K1) ? Wk[(long)k * COUT + cc] : 0.f;
        }
        __syncthreads();
        #pragma unroll
        for (int kk = 0; kk < 32; kk++) {
            float a[NR], b[NC];
            #pragma unroll
            for (int r = 0; r < NR; r++) a[r] = Gs[kk][ty + r * 16];
            #pragma unroll
            for (int c = 0; c < NC; c++) b[c] = Ws[kk][tx + c * 16];
            #pragma unroll
            for (int r = 0; r < NR; r++)
                #pragma unroll
                for (int c = 0; c < NC; c++) acc1[r][c] += a[r] * b[c];
        }
        __syncthreads();
    }

    for (int k0 = 0; k0 < CIN; k0 += 32) {
        #pragma unroll
        for (int j = 0; j < TV * 32 / 256; j++) {
            int idx = tid + j * 256;
            int r = idx >> 5, kk = idx & 31;
            int v = v0 + r, k = k0 + kk;
            Gs[kk][r] = (v < V && k < CIN) ? feat[(long)v * CIN + k] : 0.f;
        }
        #pragma unroll
        for (int j = 0; j < 32 * COUT / 256; j++) {
            int idx = tid + j * 256;
            int kk = idx / COUT, cc = idx - kk * COUT;
            int k = k0 + kk;
            Ws[kk][cc] = (k < CIN) ? Wr[(long)k * COUT + cc] : 0.f;
        }
        __syncthreads();
        #pragma unroll
        for (int kk = 0; kk < 32; kk++) {
            float a[NR], b[NC];
            #pragma unroll
            for (int r = 0; r < NR; r++) a[r] = Gs[kk][ty + r * 16];
            #pragma unroll
            for (int c = 0; c < NC; c++) b[c] = Ws[kk][tx + c * 16];
            #pragma unroll
            for (int r = 0; r < NR; r++)
                #pragma unroll
                for (int c = 0; c < NC; c++) acc2[r][c] += a[r] * b[c];
        }
        __syncthreads();
    }

    #pragma unroll
    for (int r = 0; r < NR; r++) {
        int v = v0 + ty + r * 16;
        if (v < V) {
            float inv = 1.f / fmaxf((float)deg[v], 1.f);
            long cl = 0;
            float px = 0.f, py = 0.f, pz = 0.f;
            if (POOL != 0) {
                px = pos[(long)v * 3 + 0];
                py = pos[(long)v * 3 + 1];
                pz = pos[(long)v * 3 + 2];
                int b_ = v / cellsPrev;
                int ix = min(max((int)floorf(px * nx), 0), nx - 1);
                int iy = min(max((int)floorf(py * ny), 0), ny - 1);
                int it = min(max((int)floorf(pz * nt), 0), nt - 1);
                cl = (((long)b_ * nx + ix) * ny + iy) * nt + it;
            }
            #pragma unroll
            for (int c = 0; c < NC; c++) {
                int col = tx + c * 16;
                float val = acc1[r][c] * inv + acc2[r][c] + bias[col];
                val = fmaxf(val, 0.f);
                if (WOUT) out[(long)v * COUT + col] = val;
                if (POOL == 1)
                    atomicMax((int*)(fcN + cl * (COUT + 2) + col), __float_as_int(val));
                else if (POOL == 2)
                    atomicAdd(fcN + cl * (COUT + 2) + col, val);
            }
            if (POOL != 0 && tx == 0) {
                atomicAdd(posSum + cl * 3 + 0, px);
                atomicAdd(posSum + cl * 3 + 1, py);
                atomicAdd(posSum + cl * 3 + 2, pz);
                atomicAdd(cntPool + cl, 1.0f);
            }
        }
    }
}

// ---------------------------------------------------------------------------
// Launch
// ---------------------------------------------------------------------------
static inline int cdiv(long a, long b) { return (int)((a + b - 1) / b); }

extern "C" void kernel_launch(void* const* d_in, const int* in_sizes, int n_in,
                              void* d_out, int out_size) {
    const float* x    = (const float*)d_in[0];
    const float* pos0 = (const float*)d_in[1];
    const int*   batch = (const int*)d_in[2];
    const int* e0 = (const int*)d_in[3];
    const int* e1 = (const int*)d_in[4];
    const int* e2 = (const int*)d_in[5];
    const int* e3 = (const int*)d_in[6];
    const int* e4 = (const int*)d_in[7];
    const float* W1 = (const float*)d_in[8];
    const float* R1 = (const float*)d_in[9];
    const float* b1 = (const float*)d_in[10];
    const float* W2 = (const float*)d_in[11];
    const float* R2 = (const float*)d_in[12];
    const float* b2 = (const float*)d_in[13];
    const float* W3 = (const float*)d_in[14];
    const float* R3 = (const float*)d_in[15];
    const float* b3 = (const float*)d_in[16];
    const float* W4 = (const float*)d_in[17];
    const float* R4 = (const float*)d_in[18];
    const float* b4 = (const float*)d_in[19];
    const float* W5 = (const float*)d_in[20];
    const float* R5 = (const float*)d_in[21];
    const float* b5 = (const float*)d_in[22];
    float* out = (float*)d_out;

    float* buf;
    cudaGetSymbolAddress((void**)&buf, g_buf);
    int* ip;
    cudaGetSymbolAddress((void**)&ip, g_csr);
    int* cnt = ip + I_CNT;
    int* row = ip + I_ROW;
    int* cur = ip + I_CUR;
    int* ebin = ip + I_EBIN;
    int* bs = ip + I_BS;
    int* bo = ip + I_BO;

    Batch5 P;
    P.e[0] = e0; P.e[1] = e1; P.e[2] = e2; P.e[3] = e3; P.e[4] = e4;
    P.E[0] = NE0; P.E[1] = NE1; P.E[2] = NE2; P.E[3] = NE3; P.E[4] = NE4;
    P.voff[0] = VOFF0; P.voff[1] = VOFF1; P.voff[2] = VOFF2;
    P.voff[3] = VOFF3; P.voff[4] = VOFF4;

    // Zero pool accumulators + fc buffers; zero CSR counts; build pxa.
    zero_kernel<<<512, 256>>>(buf, ZERO_N / 4);
    zeroi_kernel<<<cdiv(TOTV, 256), 256>>>(cnt, TOTV);
    pxa_kernel<<<cdiv(NV0, 256), 256>>>(pos0, x, (float4*)(buf + O_PXA), (int)NV0);

    // Batched CSR for all 5 layers
    hist5_kernel<<<dim3(256, 5), 256>>>(P, cnt);
    int nb = cdiv(TOTV, 2048);
    scan1_kernel<<<nb, 256>>>(cnt, row, bs, (int)TOTV);
    scan1_kernel<<<1, 256>>>(bs, bo, nullptr, nb);
    scan_add_kernel<<<nb, 256>>>(row, bo, (int)TOTV);
    cudaMemcpyAsync(cur, row, (size_t)TOTV * sizeof(int), cudaMemcpyDeviceToDevice, 0);
    bin5_kernel<<<dim3(256, 5), 256>>>(P, cur, ebin);

    // ---------------- Layer 1 (fused gather+gemm+maxpool into fc1) ---------
    spline1_fused_kernel<<<cdiv(NV0, 256), 256>>>(row + VOFF0, cnt + VOFF0, ebin,
        (const float4*)(buf + O_PXA), batch, W1, R1, b1,
        buf + O_FC1, buf + O_P1P, buf + O_CNT1, (int)NV0);
    finalize_kernel<16><<<cdiv(NV1, 256), 256>>>(buf + O_FC1, buf + O_P1P,
        buf + O_CNT1, (int)NV1, 0);

    // ---------------- Layer 2: Cin=18 -> Cout=64, pool -> fc2 --------------
    gather_G_kernel<18><<<cdiv(NV1, 8), 256>>>(row + VOFF1, cnt + VOFF1, ebin,
        buf + O_P1P, buf + O_FC1, buf + O_G2, (int)NV1, 10.0f);
    spline_gemm_kernel<18, 64, 64, 1, false><<<cdiv(NV1, 64), 256>>>(
        buf + O_G2, cnt + VOFF1, buf + O_FC1, W2, R2, b2, nullptr, (int)NV1,
        buf + O_P1P, 64 * 48 * 8, 32, 24, 4,
        buf + O_FC2, buf + O_P2P, buf + O_CNT2);
    finalize_kernel<64><<<cdiv(NV2, 256), 256>>>(buf + O_FC2, buf + O_P2P,
        buf + O_CNT2, (int)NV2, 0);

    // ---------------- Layer 3: Cin=66 -> Cout=128, pool -> fc3 -------------
    gather_G_kernel<66><<<cdiv(NV2, 8), 256>>>(row + VOFF2, cnt + VOFF2, ebin,
        buf + O_P2P, buf + O_FC2, buf + O_G3, (int)NV2, 6.0f);
    spline_gemm_kernel<66, 128, 64, 1, false><<<cdiv(NV2, 64), 256>>>(
        buf + O_G3, cnt + VOFF2, buf + O_FC2, W3, R3, b3, nullptr, (int)NV2,
        buf + O_P2P, 32 * 24 * 4, 16, 12, 2,
        buf + O_FC3, buf + O_P3P, buf + O_CNT3);
    finalize_kernel<128><<<cdiv(NV3, 256), 256>>>(buf + O_FC3, buf + O_P3P,
        buf + O_CNT3, (int)NV3, 0);

    // ---------------- Layer 4: Cin=130 -> Cout=128, out3 + meanpool -> fc4 -
    gather_G_kernel<130><<<cdiv(NV3, 8), 256>>>(row + VOFF3, cnt + VOFF3, ebin,
        buf + O_P3P, buf + O_FC3, buf + O_G4, (int)NV3, 3.0f);
    spline_gemm_kernel<130, 128, 32, 2, true><<<cdiv(NV3, 32), 256>>>(
        buf + O_G4, cnt + VOFF3, buf + O_FC3, W4, R4, b4, out, (int)NV3,
        buf + O_P3P, 16 * 12 * 2, 8, 6, 1,
        buf + O_FC4, buf + O_P4P, buf + O_CNT4);
    finalize_kernel<128><<<cdiv(NV4, 256), 256>>>(buf + O_FC4, buf + O_P4P,
        buf + O_CNT4, (int)NV4, 1);

    // ---------------- Layer 5: Cin=130 -> Cout=128, writes out tail --------
    gather_G_kernel<130><<<cdiv(NV4, 8), 256>>>(row + VOFF4, cnt + VOFF4, ebin,
        buf + O_P4P, buf + O_FC4, buf + O_G5, (int)NV4, 1.5f);
    spline_gemm_kernel<130, 128, 32, 0, true><<<cdiv(NV4, 32), 256>>>(
        buf + O_G5, cnt + VOFF4, buf + O_FC4, W5, R5, b5, out + NV3 * 128, (int)NV4,
        nullptr, 1, 1, 1, 1, nullptr, nullptr, nullptr);
}

// round 5
// speedup vs baseline: 2.3278x; 1.0092x over previous
#include <cuda_runtime.h>
#include <cuda_bf16.h>

// ---------------------------------------------------------------------------
// Problem constants
// ---------------------------------------------------------------------------
constexpr long NV0 = 300000, NV1 = 98304, NV2 = 12288, NV3 = 1536, NV4 = 192;
constexpr long NE0 = 3600000, NE1 = 786432, NE2 = 196608, NE3 = 24576, NE4 = 3072;
constexpr long TOTV = NV0 + NV1 + NV2 + NV3 + NV4;
constexpr long TOTE = NE0 + NE1 + NE2 + NE3 + NE4;

// ---------------------------------------------------------------------------
// Float scratch. Zero-region first: fc (pool targets) + posSum + pool counts.
// ---------------------------------------------------------------------------
constexpr long O_FC1 = 0;                      // [NV1, 18]
constexpr long O_FC2 = O_FC1 + NV1 * 18;       // [NV2, 66]
constexpr long O_FC3 = O_FC2 + NV2 * 66;       // [NV3, 130]
constexpr long O_FC4 = O_FC3 + NV3 * 130;      // [NV4, 130]
constexpr long O_P1P = O_FC4 + NV4 * 130;
constexpr long O_P2P = O_P1P + NV1 * 3;
constexpr long O_P3P = O_P2P + NV2 * 3;
constexpr long O_P4P = O_P3P + NV3 * 3;
constexpr long O_CNT1 = O_P4P + NV4 * 3;
constexpr long O_CNT2 = O_CNT1 + NV1;
constexpr long O_CNT3 = O_CNT2 + NV2;
constexpr long O_CNT4 = O_CNT3 + NV3;
constexpr long ZERO_N = O_CNT4 + NV4;          // zeroed each run
// not zeroed:
constexpr long O_PXA = (ZERO_N + 3) & ~3L;     // [NV0] float4
constexpr long O_G2  = O_PXA + NV0 * 4;
constexpr long O_G3  = O_G2 + NV1 * 144;
constexpr long O_G4  = O_G3 + NV2 * 528;
constexpr long O_G5  = O_G4 + NV3 * 1040;
constexpr long TOTAL_N = O_G5 + NV4 * 1040;

__device__ __align__(16) float g_buf[TOTAL_N];

// Int scratch: concatenated CSR over all 5 layers.
constexpr long I_CNT = 0;
constexpr long I_ROW = I_CNT + TOTV;
constexpr long I_CUR = I_ROW + TOTV;
constexpr long I_EBIN = I_CUR + TOTV;
constexpr long I_BS  = I_EBIN + TOTE;
constexpr long I_BO  = I_BS + 2048;
constexpr long TOTAL_I = I_BO + 2048;

__device__ __align__(16) int g_csr[TOTAL_I];

constexpr int VOFF0 = 0;
constexpr int VOFF1 = (int)NV0;
constexpr int VOFF2 = (int)(NV0 + NV1);
constexpr int VOFF3 = (int)(NV0 + NV1 + NV2);
constexpr int VOFF4 = (int)(NV0 + NV1 + NV2 + NV3);

struct Batch5 {
    const int* e[5];
    long E[5];
    int voff[5];
};

// ---------------------------------------------------------------------------
// Zero kernels
// ---------------------------------------------------------------------------
__global__ void zero_kernel(float* __restrict__ p, long n4) {
    float4* p4 = reinterpret_cast<float4*>(p);
    long i = (long)blockIdx.x * blockDim.x + threadIdx.x;
    long stride = (long)gridDim.x * blockDim.x;
    float4 z = make_float4(0.f, 0.f, 0.f, 0.f);
    for (; i < n4; i += stride) p4[i] = z;
}
__global__ void zeroi_kernel(int* __restrict__ p, long n) {
    long i = (long)blockIdx.x * blockDim.x + threadIdx.x;
    if (i < n) p[i] = 0;
}

// ---------------------------------------------------------------------------
// pxa prep: pxa[v] = (pos.x, pos.y, pos.z, x[v])
// ---------------------------------------------------------------------------
__global__ void pxa_kernel(const float* __restrict__ pos, const float* __restrict__ x,
                           float4* __restrict__ pxa, int V) {
    int v = blockIdx.x * blockDim.x + threadIdx.x;
    if (v >= V) return;
    pxa[v] = make_float4(pos[(long)v * 3], pos[(long)v * 3 + 1], pos[(long)v * 3 + 2], x[v]);
}

// ---------------------------------------------------------------------------
// Batched CSR build, int4-vectorized (all E divisible by 4).
// ---------------------------------------------------------------------------
__global__ void hist5_kernel(Batch5 p, int* __restrict__ cnt) {
    int L = blockIdx.y;
    const int4* dst4 = reinterpret_cast<const int4*>(p.e[L] + p.E[L]);
    int* c = cnt + p.voff[L];
    long n4 = p.E[L] >> 2;
    long i = (long)blockIdx.x * blockDim.x + threadIdx.x;
    long stride = (long)gridDim.x * blockDim.x;
    for (; i < n4; i += stride) {
        int4 d = dst4[i];
        atomicAdd(&c[d.x], 1);
        atomicAdd(&c[d.y], 1);
        atomicAdd(&c[d.z], 1);
        atomicAdd(&c[d.w], 1);
    }
}

// 256 threads x 8 elems = 2048 per block. Exclusive scan + block sums.
// Writes both `row` and `cur` (cur is consumed/destroyed by bin5).
__global__ void scan1_kernel(const int* __restrict__ in, int* __restrict__ out,
                             int* __restrict__ out2, int* __restrict__ bsums, int n) {
    __shared__ int tot[256];
    int tid = threadIdx.x;
    long base = (long)blockIdx.x * 2048 + (long)tid * 8;
    int v[8]; int sum = 0;
    #pragma unroll
    for (int j = 0; j < 8; j++) { v[j] = (base + j < n) ? in[base + j] : 0; sum += v[j]; }
    tot[tid] = sum;
    __syncthreads();
    #pragma unroll
    for (int off = 1; off < 256; off <<= 1) {
        int t = (tid >= off) ? tot[tid - off] : 0;
        __syncthreads();
        tot[tid] += t;
        __syncthreads();
    }
    int run = (tid == 0) ? 0 : tot[tid - 1];
    #pragma unroll
    for (int j = 0; j < 8; j++) {
        if (base + j < n) {
            out[base + j] = run;
            if (out2) out2[base + j] = run;
        }
        run += v[j];
    }
    if (bsums && tid == 255) bsums[blockIdx.x] = tot[255];
}

__global__ void scan_add_kernel(int* __restrict__ out, int* __restrict__ out2,
                                const int* __restrict__ boffs, int n) {
    int add = boffs[blockIdx.x];
    long base = (long)blockIdx.x * 2048 + (long)threadIdx.x * 8;
    #pragma unroll
    for (int j = 0; j < 8; j++)
        if (base + j < n) { out[base + j] += add; out2[base + j] += add; }
}

__global__ void bin5_kernel(Batch5 p, int* __restrict__ cur, int* __restrict__ ebin) {
    int L = blockIdx.y;
    const int4* src4 = reinterpret_cast<const int4*>(p.e[L]);
    const int4* dst4 = reinterpret_cast<const int4*>(p.e[L] + p.E[L]);
    int* cu = cur + p.voff[L];
    long n4 = p.E[L] >> 2;
    long i = (long)blockIdx.x * blockDim.x + threadIdx.x;
    long stride = (long)gridDim.x * blockDim.x;
    for (; i < n4; i += stride) {
        int4 s = src4[i];
        int4 d = dst4[i];
        int p0 = atomicAdd(&cu[d.x], 1);
        int p1 = atomicAdd(&cu[d.y], 1);
        int p2 = atomicAdd(&cu[d.z], 1);
        int p3 = atomicAdd(&cu[d.w], 1);
        ebin[p0] = s.x;
        ebin[p1] = s.y;
        ebin[p2] = s.z;
        ebin[p3] = s.w;
    }
}

// ---------------------------------------------------------------------------
// Basis helper
// ---------------------------------------------------------------------------
__device__ __forceinline__ void basis8(float p0, float p1, float p2, float* b) {
    float q0 = 1.f - p0, q1 = 1.f - p1, q2 = 1.f - p2;
    float b00 = q0 * q1, b01 = p0 * q1, b10 = q0 * p1, b11 = p0 * p1;
    b[0] = b00 * q2; b[1] = b01 * q2; b[2] = b10 * q2; b[3] = b11 * q2;
    b[4] = b00 * p2; b[5] = b01 * p2; b[6] = b10 * p2; b[7] = b11 * p2;
}

// ---------------------------------------------------------------------------
// Layer 1 fused: gather (4-edge software pipeline) + 24x16 GEMM + maxpool.
// ---------------------------------------------------------------------------
__device__ __forceinline__ void s1_accum(float4 sp, float dx, float dy, float dz,
                                         float* G) {
    float p0 = __saturatef((dx - sp.x) * 20.0f + 0.5f);
    float p1 = __saturatef((dy - sp.y) * 20.0f + 0.5f);
    float p2 = __saturatef((dz - sp.z) * 20.0f + 0.5f);
    float b[8]; basis8(p0, p1, p2, b);
    #pragma unroll
    for (int s8 = 0; s8 < 8; s8++) {
        G[s8 * 3 + 0] += b[s8] * sp.w;
        G[s8 * 3 + 1] += b[s8] * sp.x;
        G[s8 * 3 + 2] += b[s8] * sp.y;
    }
}

__global__ void __launch_bounds__(256)
spline1_fused_kernel(const int* __restrict__ rowptr, const int* __restrict__ cnt,
                     const int* __restrict__ ebin,
                     const float4* __restrict__ pxa, const int* __restrict__ batch,
                     const float* __restrict__ Wk, const float* __restrict__ Wr,
                     const float* __restrict__ bias,
                     float* __restrict__ fc1, float* __restrict__ posSum,
                     float* __restrict__ cntPool, int V) {
    __shared__ float sWk[24][16];
    __shared__ float sWr[3][16];
    __shared__ float sb[16];
    int tid = threadIdx.x;
    for (int i = tid; i < 24 * 16; i += 256) sWk[i / 16][i % 16] = Wk[i];
    if (tid < 48) sWr[tid / 16][tid % 16] = Wr[tid];
    if (tid < 16) sb[tid] = bias[tid];
    __syncthreads();
    int v = blockIdx.x * 256 + tid;
    if (v >= V) return;

    float G[24];
    #pragma unroll
    for (int k = 0; k < 24; k++) G[k] = 0.f;

    float4 me = pxa[v];
    float dx = me.x, dy = me.y, dz = me.z;
    int start = rowptr[v];
    int deg = cnt[v];
    int j = 0;
    for (; j + 4 <= deg; j += 4) {
        int s0 = ebin[start + j + 0];
        int s1 = ebin[start + j + 1];
        int s2 = ebin[start + j + 2];
        int s3 = ebin[start + j + 3];
        float4 a0 = pxa[s0];
        float4 a1 = pxa[s1];
        float4 a2 = pxa[s2];
        float4 a3 = pxa[s3];
        s1_accum(a0, dx, dy, dz, G);
        s1_accum(a1, dx, dy, dz, G);
        s1_accum(a2, dx, dy, dz, G);
        s1_accum(a3, dx, dy, dz, G);
    }
    for (; j < deg; j++) {
        float4 a0 = pxa[ebin[start + j]];
        s1_accum(a0, dx, dy, dz, G);
    }

    float acc[16];
    #pragma unroll
    for (int c = 0; c < 16; c++) acc[c] = 0.f;
    #pragma unroll
    for (int k = 0; k < 24; k++) {
        float g = G[k];
        #pragma unroll
        for (int c = 0; c < 16; c++) acc[c] += g * sWk[k][c];
    }
    float inv = 1.f / fmaxf((float)deg, 1.f);

    int b_ = batch[v];
    int ix = min(max((int)floorf(dx * 64.f), 0), 63);
    int iy = min(max((int)floorf(dy * 48.f), 0), 47);
    int it = min(max((int)floorf(dz * 8.f), 0), 7);
    long cl = (((long)b_ * 64 + ix) * 48 + iy) * 8 + it;
    float* fcrow = fc1 + cl * 18;

    #pragma unroll
    for (int c = 0; c < 16; c++) {
        float val = acc[c] * inv + me.w * sWr[0][c] + dx * sWr[1][c]
                  + dy * sWr[2][c] + sb[c];
        val = fmaxf(val, 0.f);
        atomicMax((int*)(fcrow + c), __float_as_int(val));
    }
    atomicAdd(posSum + cl * 3 + 0, dx);
    atomicAdd(posSum + cl * 3 + 1, dy);
    atomicAdd(posSum + cl * 3 + 2, dz);
    atomicAdd(cntPool + cl, 1.0f);
}

// ---------------------------------------------------------------------------
// finalize
// ---------------------------------------------------------------------------
template <int C>
__global__ void finalize_kernel(float* __restrict__ fc, float* __restrict__ posSum,
                                const float* __restrict__ cnt, int V, int isMean) {
    int v = blockIdx.x * blockDim.x + threadIdx.x;
    if (v >= V) return;
    float cn = fmaxf(cnt[v], 1.0f);
    float inv = 1.0f / cn;
    float px = posSum[(long)v * 3 + 0] * inv;
    float py = posSum[(long)v * 3 + 1] * inv;
    float pz = posSum[(long)v * 3 + 2] * inv;
    posSum[(long)v * 3 + 0] = px;
    posSum[(long)v * 3 + 1] = py;
    posSum[(long)v * 3 + 2] = pz;
    float* row = fc + (long)v * (C + 2);
    row[C] = px;
    row[C + 1] = py;
    if (isMean)
        for (int k = 0; k < C; k++) row[k] *= inv;
}

// ---------------------------------------------------------------------------
// Gather G rows for layers 2..5 (warp per node, ebin holds src ids).
// ---------------------------------------------------------------------------
template <int CIN>
__global__ void __launch_bounds__(256)
gather_G_kernel(const int* __restrict__ rowptr, const int* __restrict__ cnt,
                const int* __restrict__ ebin,
                const float* __restrict__ pos, const float* __restrict__ feat,
                float* __restrict__ G, int V, float inv2mv) {
    constexpr int NJ = (CIN + 31) / 32;
    int lane = threadIdx.x & 31;
    int v = blockIdx.x * 8 + (threadIdx.x >> 5);
    if (v >= V) return;
    float dx = pos[(long)v * 3 + 0];
    float dy = pos[(long)v * 3 + 1];
    float dz = pos[(long)v * 3 + 2];
    float Gacc[NJ][8];
    #pragma unroll
    for (int jj = 0; jj < NJ; jj++)
        #pragma unroll
        for (int s8 = 0; s8 < 8; s8++) Gacc[jj][s8] = 0.f;

    int start = rowptr[v];
    int deg = cnt[v];
    for (int j = 0; j < deg; j++) {
        int s = ebin[start + j];
        float sx = pos[(long)s * 3 + 0];
        float sy = pos[(long)s * 3 + 1];
        float sz = pos[(long)s * 3 + 2];
        float p0 = __saturatef((dx - sx) * inv2mv + 0.5f);
        float p1 = __saturatef((dy - sy) * inv2mv + 0.5f);
        float p2 = __saturatef((dz - sz) * inv2mv + 0.5f);
        float b[8]; basis8(p0, p1, p2, b);
        float f[NJ];
        #pragma unroll
        for (int jj = 0; jj < NJ; jj++) {
            int idx = lane + jj * 32;
            f[jj] = (idx < CIN) ? feat[(long)s * CIN + idx] : 0.f;
        }
        #pragma unroll
        for (int s8 = 0; s8 < 8; s8++)
            #pragma unroll
            for (int jj = 0; jj < NJ; jj++) Gacc[jj][s8] += b[s8] * f[jj];
    }
    #pragma unroll
    for (int s8 = 0; s8 < 8; s8++)
        #pragma unroll
        for (int jj = 0; jj < NJ; jj++) {
            int idx = lane + jj * 32;
            if (idx < CIN) G[(long)v * (8 * CIN) + s8 * CIN + idx] = Gacc[jj][s8];
        }
}

// ---------------------------------------------------------------------------
// float4-vectorized register-tiled GEMM + fused epilogue (relu/out/pool).
// Block: 256 threads as 16x16. Tile: TV rows x COUT cols.
// Thread micro-tile: RT rows x CT col-groups of 4 (cols tx*4 + g*64).
// acc = (G@Wk); after pass 1 scaled by 1/deg; pass 2 adds feat@Wr.
// POOL: 0 none, 1 max, 2 mean.
// ---------------------------------------------------------------------------
template <int CIN, int COUT, int TV, int POOL, bool WOUT>
__global__ void __launch_bounds__(256)
spline_gemm_kernel(const float* __restrict__ G, const int* __restrict__ deg,
                   const float* __restrict__ feat,
                   const float* __restrict__ Wk, const float* __restrict__ Wr,
                   const float* __restrict__ bias,
                   float* __restrict__ out, int V,
                   const float* __restrict__ pos, int cellsPrev,
                   int nx, int ny, int nt,
                   float* __restrict__ fcN, float* __restrict__ posSum,
                   float* __restrict__ cntPool) {
    constexpr int K1 = 8 * CIN;
    constexpr int RT = TV / 16;
    constexpr int CT = COUT / 64;
    __shared__ float Gs[TV][36];          // row-major, pad 36 (16B-aligned rows)
    __shared__ float Ws[32][COUT];
    int tid = threadIdx.x;
    int tx = tid & 15, ty = tid >> 4;
    int v0 = blockIdx.x * TV;

    float4 acc[RT][CT];
    #pragma unroll
    for (int i = 0; i < RT; i++)
        #pragma unroll
        for (int g = 0; g < CT; g++) acc[i][g] = make_float4(0.f, 0.f, 0.f, 0.f);

    // ---- Pass 1: G @ Wk ----
    for (int k0 = 0; k0 < K1; k0 += 32) {
        #pragma unroll
        for (int j = 0; j < TV * 32 / 256; j++) {
            int idx = tid + j * 256;
            int r = idx >> 5, kk = idx & 31;
            int v = v0 + r, k = k0 + kk;
            Gs[r][kk] = (v < V && k < K1) ? G[(long)v * K1 + k] : 0.f;
        }
        #pragma unroll
        for (int j = 0; j < 32 * COUT / 256; j++) {
            int idx = tid + j * 256;
            int kk = idx / COUT, cc = idx - kk * COUT;
            int k = k0 + kk;
            Ws[kk][cc] = (k < K1) ? Wk[(long)k * COUT + cc] : 0.f;
        }
        __syncthreads();
        #pragma unroll
        for (int kq = 0; kq < 8; kq++) {
            float4 a[RT];
            #pragma unroll
            for (int i = 0; i < RT; i++)
                a[i] = *(const float4*)&Gs[ty * RT + i][kq * 4];
            float4 b[4][CT];
            #pragma unroll
            for (int t = 0; t < 4; t++)
                #pragma unroll
                for (int g = 0; g < CT; g++)
                    b[t][g] = *(const float4*)&Ws[kq * 4 + t][g * 64 + tx * 4];
            #pragma unroll
            for (int i = 0; i < RT; i++) {
                float av[4] = {a[i].x, a[i].y, a[i].z, a[i].w};
                #pragma unroll
                for (int t = 0; t < 4; t++)
                    #pragma unroll
                    for (int g = 0; g < CT; g++) {
                        acc[i][g].x += av[t] * b[t][g].x;
                        acc[i][g].y += av[t] * b[t][g].y;
                        acc[i][g].z += av[t] * b[t][g].z;
                        acc[i][g].w += av[t] * b[t][g].w;
                    }
            }
        }
        __syncthreads();
    }

    // ---- scale by 1/deg ----
    #pragma unroll
    for (int i = 0; i < RT; i++) {
        int v = v0 + ty * RT + i;
        float inv = (v < V) ? 1.f / fmaxf((float)deg[v], 1.f) : 0.f;
        #pragma unroll
        for (int g = 0; g < CT; g++) {
            acc[i][g].x *= inv; acc[i][g].y *= inv;
            acc[i][g].z *= inv; acc[i][g].w *= inv;
        }
    }

    // ---- Pass 2: feat @ Wr ----
    for (int k0 = 0; k0 < CIN; k0 += 32) {
        #pragma unroll
        for (int j = 0; j < TV * 32 / 256; j++) {
            int idx = tid + j * 256;
            int r = idx >> 5, kk = idx & 31;
            int v = v0 + r, k = k0 + kk;
            Gs[r][kk] = (v < V && k < CIN) ? feat[(long)v * CIN + k] : 0.f;
        }
        #pragma unroll
        for (int j = 0; j < 32 * COUT / 256; j++) {
            int idx = tid + j * 256;
            int kk = idx / COUT, cc = idx - kk * COUT;
            int k = k0 + kk;
            Ws[kk][cc] = (k < CIN) ? Wr[(long)k * COUT + cc] : 0.f;
        }
        __syncthreads();
        #pragma unroll
        for (int kq = 0; kq < 8; kq++) {
            float4 a[RT];
            #pragma unroll
            for (int i = 0; i < RT; i++)
                a[i] = *(const float4*)&Gs[ty * RT + i][kq * 4];
            float4 b[4][CT];
            #pragma unroll
            for (int t = 0; t < 4; t++)
                #pragma unroll
                for (int g = 0; g < CT; g++)
                    b[t][g] = *(const float4*)&Ws[kq * 4 + t][g * 64 + tx * 4];
            #pragma unroll
            for (int i = 0; i < RT; i++) {
                float av[4] = {a[i].x, a[i].y, a[i].z, a[i].w};
                #pragma unroll
                for (int t = 0; t < 4; t++)
                    #pragma unroll
                    for (int g = 0; g < CT; g++) {
                        acc[i][g].x += av[t] * b[t][g].x;
                        acc[i][g].y += av[t] * b[t][g].y;
                        acc[i][g].z += av[t] * b[t][g].z;
                        acc[i][g].w += av[t] * b[t][g].w;
                    }
            }
        }
        __syncthreads();
    }

    // ---- Epilogue ----
    #pragma unroll
    for (int i = 0; i < RT; i++) {
        int v = v0 + ty * RT + i;
        if (v >= V) continue;
        long cl = 0;
        float px = 0.f, py = 0.f, pz = 0.f;
        if (POOL != 0) {
            px = pos[(long)v * 3 + 0];
            py = pos[(long)v * 3 + 1];
            pz = pos[(long)v * 3 + 2];
            int b_ = v / cellsPrev;
            int ix = min(max((int)floorf(px * nx), 0), nx - 1);
            int iy = min(max((int)floorf(py * ny), 0), ny - 1);
            int it = min(max((int)floorf(pz * nt), 0), nt - 1);
            cl = (((long)b_ * nx + ix) * ny + iy) * nt + it;
        }
        #pragma unroll
        for (int g = 0; g < CT; g++) {
            int col0 = g * 64 + tx * 4;
            float vals[4] = {acc[i][g].x, acc[i][g].y, acc[i][g].z, acc[i][g].w};
            #pragma unroll
            for (int u = 0; u < 4; u++) {
                int col = col0 + u;
                float val = fmaxf(vals[u] + bias[col], 0.f);
                if (WOUT) out[(long)v * COUT + col] = val;
                if (POOL == 1)
                    atomicMax((int*)(fcN + cl * (COUT + 2) + col), __float_as_int(val));
                else if (POOL == 2)
                    atomicAdd(fcN + cl * (COUT + 2) + col, val);
            }
        }
        if (POOL != 0 && tx == 0) {
            atomicAdd(posSum + cl * 3 + 0, px);
            atomicAdd(posSum + cl * 3 + 1, py);
            atomicAdd(posSum + cl * 3 + 2, pz);
            atomicAdd(cntPool + cl, 1.0f);
        }
    }
}

// ---------------------------------------------------------------------------
// Launch
// ---------------------------------------------------------------------------
static inline int cdiv(long a, long b) { return (int)((a + b - 1) / b); }

extern "C" void kernel_launch(void* const* d_in, const int* in_sizes, int n_in,
                              void* d_out, int out_size) {
    const float* x    = (const float*)d_in[0];
    const float* pos0 = (const float*)d_in[1];
    const int*   batch = (const int*)d_in[2];
    const int* e0 = (const int*)d_in[3];
    const int* e1 = (const int*)d_in[4];
    const int* e2 = (const int*)d_in[5];
    const int* e3 = (const int*)d_in[6];
    const int* e4 = (const int*)d_in[7];
    const float* W1 = (const float*)d_in[8];
    const float* R1 = (const float*)d_in[9];
    const float* b1 = (const float*)d_in[10];
    const float* W2 = (const float*)d_in[11];
    const float* R2 = (const float*)d_in[12];
    const float* b2 = (const float*)d_in[13];
    const float* W3 = (const float*)d_in[14];
    const float* R3 = (const float*)d_in[15];
    const float* b3 = (const float*)d_in[16];
    const float* W4 = (const float*)d_in[17];
    const float* R4 = (const float*)d_in[18];
    const float* b4 = (const float*)d_in[19];
    const float* W5 = (const float*)d_in[20];
    const float* R5 = (const float*)d_in[21];
    const float* b5 = (const float*)d_in[22];
    float* out = (float*)d_out;

    float* buf;
    cudaGetSymbolAddress((void**)&buf, g_buf);
    int* ip;
    cudaGetSymbolAddress((void**)&ip, g_csr);
    int* cnt = ip + I_CNT;
    int* row = ip + I_ROW;
    int* cur = ip + I_CUR;
    int* ebin = ip + I_EBIN;
    int* bs = ip + I_BS;
    int* bo = ip + I_BO;

    Batch5 P;
    P.e[0] = e0; P.e[1] = e1; P.e[2] = e2; P.e[3] = e3; P.e[4] = e4;
    P.E[0] = NE0; P.E[1] = NE1; P.E[2] = NE2; P.E[3] = NE3; P.E[4] = NE4;
    P.voff[0] = VOFF0; P.voff[1] = VOFF1; P.voff[2] = VOFF2;
    P.voff[3] = VOFF3; P.voff[4] = VOFF4;

    zero_kernel<<<512, 256>>>(buf, ZERO_N / 4);
    zeroi_kernel<<<cdiv(TOTV, 256), 256>>>(cnt, TOTV);
    pxa_kernel<<<cdiv(NV0, 256), 256>>>(pos0, x, (float4*)(buf + O_PXA), (int)NV0);

    hist5_kernel<<<dim3(160, 5), 256>>>(P, cnt);
    int nb = cdiv(TOTV, 2048);
    scan1_kernel<<<nb, 256>>>(cnt, row, cur, bs, (int)TOTV);
    scan1_kernel<<<1, 256>>>(bs, bo, nullptr, nullptr, nb);
    scan_add_kernel<<<nb, 256>>>(row, cur, bo, (int)TOTV);
    bin5_kernel<<<dim3(160, 5), 256>>>(P, cur, ebin);

    // ---------------- Layer 1 ----------------
    spline1_fused_kernel<<<cdiv(NV0, 256), 256>>>(row + VOFF0, cnt + VOFF0, ebin,
        (const float4*)(buf + O_PXA), batch, W1, R1, b1,
        buf + O_FC1, buf + O_P1P, buf + O_CNT1, (int)NV0);
    finalize_kernel<16><<<cdiv(NV1, 256), 256>>>(buf + O_FC1, buf + O_P1P,
        buf + O_CNT1, (int)NV1, 0);

    // ---------------- Layer 2 ----------------
    gather_G_kernel<18><<<cdiv(NV1, 8), 256>>>(row + VOFF1, cnt + VOFF1, ebin,
        buf + O_P1P, buf + O_FC1, buf + O_G2, (int)NV1, 10.0f);
    spline_gemm_kernel<18, 64, 64, 1, false><<<cdiv(NV1, 64), 256>>>(
        buf + O_G2, cnt + VOFF1, buf + O_FC1, W2, R2, b2, nullptr, (int)NV1,
        buf + O_P1P, 64 * 48 * 8, 32, 24, 4,
        buf + O_FC2, buf + O_P2P, buf + O_CNT2);
    finalize_kernel<64><<<cdiv(NV2, 256), 256>>>(buf + O_FC2, buf + O_P2P,
        buf + O_CNT2, (int)NV2, 0);

    // ---------------- Layer 3 ----------------
    gather_G_kernel<66><<<cdiv(NV2, 8), 256>>>(row + VOFF2, cnt + VOFF2, ebin,
        buf + O_P2P, buf + O_FC2, buf + O_G3, (int)NV2, 6.0f);
    spline_gemm_kernel<66, 128, 64, 1, false><<<cdiv(NV2, 64), 256>>>(
        buf + O_G3, cnt + VOFF2, buf + O_FC2, W3, R3, b3, nullptr, (int)NV2,
        buf + O_P2P, 32 * 24 * 4, 16, 12, 2,
        buf + O_FC3, buf + O_P3P, buf + O_CNT3);
    finalize_kernel<128><<<cdiv(NV3, 256), 256>>>(buf + O_FC3, buf + O_P3P,
        buf + O_CNT3, (int)NV3, 0);

    // ---------------- Layer 4 ----------------
    gather_G_kernel<130><<<cdiv(NV3, 8), 256>>>(row + VOFF3, cnt + VOFF3, ebin,
        buf + O_P3P, buf + O_FC3, buf + O_G4, (int)NV3, 3.0f);
    spline_gemm_kernel<130, 128, 32, 2, true><<<cdiv(NV3, 32), 256>>>(
        buf + O_G4, cnt + VOFF3, buf + O_FC3, W4, R4, b4, out, (int)NV3,
        buf + O_P3P, 16 * 12 * 2, 8, 6, 1,
        buf + O_FC4, buf + O_P4P, buf + O_CNT4);
    finalize_kernel<128><<<cdiv(NV4, 256), 256>>>(buf + O_FC4, buf + O_P4P,
        buf + O_CNT4, (int)NV4, 1);

    // ---------------- Layer 5 ----------------
    gather_G_kernel<130><<<cdiv(NV4, 8), 256>>>(row + VOFF4, cnt + VOFF4, ebin,
        buf + O_P4P, buf + O_FC4, buf + O_G5, (int)NV4, 1.5f);
    spline_gemm_kernel<130, 128, 32, 0, true><<<cdiv(NV4, 32), 256>>>(
        buf + O_G5, cnt + VOFF4, buf + O_FC4, W5, R5, b5, out + NV3 * 128, (int)NV4,
        nullptr, 1, 1, 1, 1, nullptr, nullptr, nullptr);
}

// round 7
// speedup vs baseline: 2.3352x; 1.0032x over previous
#include <cuda_runtime.h>
#include <cuda_bf16.h>

// ---------------------------------------------------------------------------
// Problem constants
// ---------------------------------------------------------------------------
constexpr long NV0 = 300000, NV1 = 98304, NV2 = 12288, NV3 = 1536, NV4 = 192;
constexpr long NE0 = 3600000, NE1 = 786432, NE2 = 196608, NE3 = 24576, NE4 = 3072;
constexpr long TOTV = NV0 + NV1 + NV2 + NV3 + NV4;
constexpr long TOTE = NE0 + NE1 + NE2 + NE3 + NE4;

// ---------------------------------------------------------------------------
// Float scratch. Zero-region first: fc (pool targets) + posSum + pool counts.
// ---------------------------------------------------------------------------
constexpr long O_FC1 = 0;                      // [NV1, 18]
constexpr long O_FC2 = O_FC1 + NV1 * 18;       // [NV2, 66]
constexpr long O_FC3 = O_FC2 + NV2 * 66;       // [NV3, 130]
constexpr long O_FC4 = O_FC3 + NV3 * 130;      // [NV4, 130]
constexpr long O_P1P = O_FC4 + NV4 * 130;
constexpr long O_P2P = O_P1P + NV1 * 3;
constexpr long O_P3P = O_P2P + NV2 * 3;
constexpr long O_P4P = O_P3P + NV3 * 3;
constexpr long O_CNT1 = O_P4P + NV4 * 3;
constexpr long O_CNT2 = O_CNT1 + NV1;
constexpr long O_CNT3 = O_CNT2 + NV2;
constexpr long O_CNT4 = O_CNT3 + NV3;
constexpr long ZERO_N = O_CNT4 + NV4;          // zeroed each run (mult of 4)
constexpr long O_PXA = (ZERO_N + 3) & ~3L;     // [NV0] float4
constexpr long TOTAL_N = O_PXA + NV0 * 4;

__device__ __align__(16) float g_buf[TOTAL_N];

// Int scratch: concatenated CSR over all 5 layers.
constexpr long I_CNT = 0;
constexpr long I_ROW = I_CNT + TOTV;
constexpr long I_CUR = I_ROW + TOTV;
constexpr long I_EBIN = I_CUR + TOTV;
constexpr long I_BS  = I_EBIN + TOTE;
constexpr long I_BO  = I_BS + 2048;
constexpr long TOTAL_I = I_BO + 2048;

__device__ __align__(16) int g_csr[TOTAL_I];

constexpr int VOFF0 = 0;
constexpr int VOFF1 = (int)NV0;
constexpr int VOFF2 = (int)(NV0 + NV1);
constexpr int VOFF3 = (int)(NV0 + NV1 + NV2);
constexpr int VOFF4 = (int)(NV0 + NV1 + NV2 + NV3);

struct Batch5 {
    const int* e[5];
    long E[5];
    int voff[5];
};

// ---------------------------------------------------------------------------
// init: zero float region, zero CSR counts, build pxa = (pos, x)
// ---------------------------------------------------------------------------
__global__ void init_kernel(float* __restrict__ buf, int* __restrict__ cnt,
                            const float* __restrict__ pos, const float* __restrict__ x) {
    long t = (long)blockIdx.x * blockDim.x + threadIdx.x;
    long T = (long)gridDim.x * blockDim.x;
    float4 z = make_float4(0.f, 0.f, 0.f, 0.f);
    float4* b4 = reinterpret_cast<float4*>(buf);
    for (long i = t; i < ZERO_N / 4; i += T) b4[i] = z;
    for (long i = t; i < TOTV; i += T) cnt[i] = 0;
    float4* pxa = reinterpret_cast<float4*>(buf + O_PXA);
    for (long v = t; v < NV0; v += T)
        pxa[v] = make_float4(pos[v * 3], pos[v * 3 + 1], pos[v * 3 + 2], x[v]);
}

// ---------------------------------------------------------------------------
// Batched CSR build. One-shot kernels: each thread issues 4 independent int4
// loads (16 edges) up-front for MLP, then the atomic batch.
// ---------------------------------------------------------------------------
__global__ void __launch_bounds__(256)
hist5_kernel(Batch5 p, int* __restrict__ cnt) {
    int L = blockIdx.y;
    long n4 = p.E[L] >> 2;
    const int4* dst4 = reinterpret_cast<const int4*>(p.e[L] + p.E[L]);
    int* c = cnt + p.voff[L];
    long T = (long)gridDim.x * blockDim.x;
    long t = (long)blockIdx.x * blockDim.x + threadIdx.x;
    int4 d[4]; bool g[4];
    #pragma unroll
    for (int u = 0; u < 4; u++) {
        long i = t + (long)u * T;
        g[u] = i < n4;
        if (g[u]) d[u] = dst4[i];
    }
    #pragma unroll
    for (int u = 0; u < 4; u++) {
        if (g[u]) {
            atomicAdd(&c[d[u].x], 1);
            atomicAdd(&c[d[u].y], 1);
            atomicAdd(&c[d[u].z], 1);
            atomicAdd(&c[d[u].w], 1);
        }
    }
}

__global__ void scan1_kernel(const int* __restrict__ in, int* __restrict__ out,
                             int* __restrict__ out2, int* __restrict__ bsums, int n) {
    __shared__ int tot[256];
    int tid = threadIdx.x;
    long base = (long)blockIdx.x * 2048 + (long)tid * 8;
    int v[8]; int sum = 0;
    #pragma unroll
    for (int j = 0; j < 8; j++) { v[j] = (base + j < n) ? in[base + j] : 0; sum += v[j]; }
    tot[tid] = sum;
    __syncthreads();
    #pragma unroll
    for (int off = 1; off < 256; off <<= 1) {
        int t = (tid >= off) ? tot[tid - off] : 0;
        __syncthreads();
        tot[tid] += t;
        __syncthreads();
    }
    int run = (tid == 0) ? 0 : tot[tid - 1];
    #pragma unroll
    for (int j = 0; j < 8; j++) {
        if (base + j < n) {
            out[base + j] = run;
            if (out2) out2[base + j] = run;
        }
        run += v[j];
    }
    if (bsums && tid == 255) bsums[blockIdx.x] = tot[255];
}

__global__ void scan_add_kernel(int* __restrict__ out, int* __restrict__ out2,
                                const int* __restrict__ boffs, int n) {
    int add = boffs[blockIdx.x];
    long base = (long)blockIdx.x * 2048 + (long)threadIdx.x * 8;
    #pragma unroll
    for (int j = 0; j < 8; j++)
        if (base + j < n) { out[base + j] += add; out2[base + j] += add; }
}

__global__ void __launch_bounds__(256)
bin5_kernel(Batch5 p, int* __restrict__ cur, int* __restrict__ ebin) {
    int L = blockIdx.y;
    long n4 = p.E[L] >> 2;
    const int4* src4 = reinterpret_cast<const int4*>(p.e[L]);
    const int4* dst4 = reinterpret_cast<const int4*>(p.e[L] + p.E[L]);
    int* cu = cur + p.voff[L];
    long T = (long)gridDim.x * blockDim.x;
    long t = (long)blockIdx.x * blockDim.x + threadIdx.x;
    int4 s[4], d[4]; bool g[4];
    #pragma unroll
    for (int u = 0; u < 4; u++) {
        long i = t + (long)u * T;
        g[u] = i < n4;
        if (g[u]) { s[u] = src4[i]; d[u] = dst4[i]; }
    }
    #pragma unroll
    for (int u = 0; u < 4; u++) {
        if (g[u]) {
            int p0 = atomicAdd(&cu[d[u].x], 1);
            int p1 = atomicAdd(&cu[d[u].y], 1);
            int p2 = atomicAdd(&cu[d[u].z], 1);
            int p3 = atomicAdd(&cu[d[u].w], 1);
            ebin[p0] = s[u].x;
            ebin[p1] = s[u].y;
            ebin[p2] = s[u].z;
            ebin[p3] = s[u].w;
        }
    }
}

// ---------------------------------------------------------------------------
// Basis helper
// ---------------------------------------------------------------------------
__device__ __forceinline__ void basis8(float p0, float p1, float p2, float* b) {
    float q0 = 1.f - p0, q1 = 1.f - p1, q2 = 1.f - p2;
    float b00 = q0 * q1, b01 = p0 * q1, b10 = q0 * p1, b11 = p0 * p1;
    b[0] = b00 * q2; b[1] = b01 * q2; b[2] = b10 * q2; b[3] = b11 * q2;
    b[4] = b00 * p2; b[5] = b01 * p2; b[6] = b10 * p2; b[7] = b11 * p2;
}

// ---------------------------------------------------------------------------
// Layer 1 fused: gather (4-edge pipeline) + 24x16 GEMM + maxpool into fc1.
// ---------------------------------------------------------------------------
__device__ __forceinline__ void s1_accum(float4 sp, float dx, float dy, float dz,
                                         float* G) {
    float p0 = __saturatef((dx - sp.x) * 20.0f + 0.5f);
    float p1 = __saturatef((dy - sp.y) * 20.0f + 0.5f);
    float p2 = __saturatef((dz - sp.z) * 20.0f + 0.5f);
    float b[8]; basis8(p0, p1, p2, b);
    #pragma unroll
    for (int s8 = 0; s8 < 8; s8++) {
        G[s8 * 3 + 0] += b[s8] * sp.w;
        G[s8 * 3 + 1] += b[s8] * sp.x;
        G[s8 * 3 + 2] += b[s8] * sp.y;
    }
}

__global__ void __launch_bounds__(256)
spline1_fused_kernel(const int* __restrict__ rowptr, const int* __restrict__ cnt,
                     const int* __restrict__ ebin,
                     const float4* __restrict__ pxa, const int* __restrict__ batch,
                     const float* __restrict__ Wk, const float* __restrict__ Wr,
                     const float* __restrict__ bias,
                     float* __restrict__ fc1, float* __restrict__ posSum,
                     float* __restrict__ cntPool, int V) {
    __shared__ float sWk[24][16];
    __shared__ float sWr[3][16];
    __shared__ float sb[16];
    int tid = threadIdx.x;
    for (int i = tid; i < 24 * 16; i += 256) sWk[i / 16][i % 16] = Wk[i];
    if (tid < 48) sWr[tid / 16][tid % 16] = Wr[tid];
    if (tid < 16) sb[tid] = bias[tid];
    __syncthreads();
    int v = blockIdx.x * 256 + tid;
    if (v >= V) return;

    float G[24];
    #pragma unroll
    for (int k = 0; k < 24; k++) G[k] = 0.f;

    float4 me = pxa[v];
    float dx = me.x, dy = me.y, dz = me.z;
    int start = rowptr[v];
    int deg = cnt[v];
    int j = 0;
    for (; j + 4 <= deg; j += 4) {
        int s0 = ebin[start + j + 0];
        int s1 = ebin[start + j + 1];
        int s2 = ebin[start + j + 2];
        int s3 = ebin[start + j + 3];
        float4 a0 = pxa[s0];
        float4 a1 = pxa[s1];
        float4 a2 = pxa[s2];
        float4 a3 = pxa[s3];
        s1_accum(a0, dx, dy, dz, G);
        s1_accum(a1, dx, dy, dz, G);
        s1_accum(a2, dx, dy, dz, G);
        s1_accum(a3, dx, dy, dz, G);
    }
    for (; j < deg; j++) {
        float4 a0 = pxa[ebin[start + j]];
        s1_accum(a0, dx, dy, dz, G);
    }

    float acc[16];
    #pragma unroll
    for (int c = 0; c < 16; c++) acc[c] = 0.f;
    #pragma unroll
    for (int k = 0; k < 24; k++) {
        float g = G[k];
        #pragma unroll
        for (int c = 0; c < 16; c++) acc[c] += g * sWk[k][c];
    }
    float inv = 1.f / fmaxf((float)deg, 1.f);

    int b_ = batch[v];
    int ix = min(max((int)floorf(dx * 64.f), 0), 63);
    int iy = min(max((int)floorf(dy * 48.f), 0), 47);
    int it = min(max((int)floorf(dz * 8.f), 0), 7);
    long cl = (((long)b_ * 64 + ix) * 48 + iy) * 8 + it;
    float* fcrow = fc1 + cl * 18;

    #pragma unroll
    for (int c = 0; c < 16; c++) {
        float val = acc[c] * inv + me.w * sWr[0][c] + dx * sWr[1][c]
                  + dy * sWr[2][c] + sb[c];
        val = fmaxf(val, 0.f);
        atomicMax((int*)(fcrow + c), __float_as_int(val));
    }
    atomicAdd(posSum + cl * 3 + 0, dx);
    atomicAdd(posSum + cl * 3 + 1, dy);
    atomicAdd(posSum + cl * 3 + 2, dz);
    atomicAdd(cntPool + cl, 1.0f);
}

// ---------------------------------------------------------------------------
// finalize
// ---------------------------------------------------------------------------
template <int C>
__global__ void finalize_kernel(float* __restrict__ fc, float* __restrict__ posSum,
                                const float* __restrict__ cnt, int V, int isMean) {
    int v = blockIdx.x * blockDim.x + threadIdx.x;
    if (v >= V) return;
    float cn = fmaxf(cnt[v], 1.0f);
    float inv = 1.0f / cn;
    float px = posSum[(long)v * 3 + 0] * inv;
    float py = posSum[(long)v * 3 + 1] * inv;
    float pz = posSum[(long)v * 3 + 2] * inv;
    posSum[(long)v * 3 + 0] = px;
    posSum[(long)v * 3 + 1] = py;
    posSum[(long)v * 3 + 2] = pz;
    float* row = fc + (long)v * (C + 2);
    row[C] = px;
    row[C + 1] = py;
    if (isMean)
        for (int k = 0; k < C; k++) row[k] *= inv;
}

// ---------------------------------------------------------------------------
// Fully fused layer (2..5): per-block gather of G rows into dynamic smem,
// then register-tiled GEMM + root + bias + relu + optional pool / out-write.
// Requires V % TV == 0 (true for all layers). POOL: 0 none, 1 max, 2 mean.
// ---------------------------------------------------------------------------
__host__ __device__ constexpr int pad4(int x) { return (x + 3) & ~3; }
__host__ __device__ constexpr int cinp_of(int CIN) {
    return pad4(CIN) + ((pad4(CIN) == CIN) ? 4 : 0);
}

template <int CIN, int COUT, int TV, int POOL, bool WOUT>
__global__ void __launch_bounds__(256)
spline_fused_kernel(const int* __restrict__ rowptr, const int* __restrict__ cnt,
                    const int* __restrict__ ebin,
                    const float* __restrict__ pos,   // [V,3] (normalized)
                    const float* __restrict__ feat,  // [V,CIN]
                    const float* __restrict__ Wk, const float* __restrict__ Wr,
                    const float* __restrict__ bias,
                    float* __restrict__ out, int V, float inv2mv,
                    int cellsPrev, int nx, int ny, int nt,
                    float* __restrict__ fcN, float* __restrict__ posSum,
                    float* __restrict__ cntPool) {
    constexpr int K1 = 8 * CIN;
    constexpr int K1P = K1 + 4;          // K1 mult of 8 -> pad keeps 16B align
    constexpr int CINP = cinp_of(CIN);
    constexpr int NJ = (CIN + 31) / 32;
    constexpr int NPW = TV / 8;
    constexpr int RT = TV / 16;
    constexpr int CT = COUT / 64;

    extern __shared__ float sm[];
    float* Gs = sm;                      // [TV][K1P]
    float* Fs = Gs + TV * K1P;           // [TV][CINP]
    float* Ws = Fs + TV * CINP;          // [32][COUT]
    float* sDeg = Ws + 32 * COUT;        // [TV]

    int tid = threadIdx.x;
    int lane = tid & 31, warp = tid >> 5;
    int v0 = blockIdx.x * TV;

    // ---- Phase 1: gather G rows + feat rows into smem ----
    for (int t = 0; t < NPW; t++) {
        int n = warp * NPW + t;
        int v = v0 + n;
        float dx = pos[(long)v * 3 + 0];
        float dy = pos[(long)v * 3 + 1];
        float dz = pos[(long)v * 3 + 2];
        int start = rowptr[v];
        int deg = cnt[v];
        float Gacc[NJ][8];
        #pragma unroll
        for (int jj = 0; jj < NJ; jj++)
            #pragma unroll
            for (int s8 = 0; s8 < 8; s8++) Gacc[jj][s8] = 0.f;
        for (int j = 0; j < deg; j++) {
            int s = ebin[start + j];
            float sx = pos[(long)s * 3 + 0];
            float sy = pos[(long)s * 3 + 1];
            float sz = pos[(long)s * 3 + 2];
            float p0 = __saturatef((dx - sx) * inv2mv + 0.5f);
            float p1 = __saturatef((dy - sy) * inv2mv + 0.5f);
            float p2 = __saturatef((dz - sz) * inv2mv + 0.5f);
            float b[8]; basis8(p0, p1, p2, b);
            float f[NJ];
            #pragma unroll
            for (int jj = 0; jj < NJ; jj++) {
                int idx = lane + jj * 32;
                f[jj] = (idx < CIN) ? feat[(long)s * CIN + idx] : 0.f;
            }
            #pragma unroll
            for (int s8 = 0; s8 < 8; s8++)
                #pragma unroll
                for (int jj = 0; jj < NJ; jj++) Gacc[jj][s8] += b[s8] * f[jj];
        }
        #pragma unroll
        for (int s8 = 0; s8 < 8; s8++)
            #pragma unroll
            for (int jj = 0; jj < NJ; jj++) {
                int idx = lane + jj * 32;
                if (idx < CIN) Gs[(long)n * K1P + s8 * CIN + idx] = Gacc[jj][s8];
            }
        #pragma unroll
        for (int jj = 0; jj < NJ; jj++) {
            int idx = lane + jj * 32;
            if (idx < CIN) Fs[n * CINP + idx] = feat[(long)v * CIN + idx];
        }
        if (lane == 0) sDeg[n] = 1.f / fmaxf((float)deg, 1.f);
    }
    __syncthreads();

    // ---- Phase 2: GEMM ----
    int tx = tid & 15, ty = tid >> 4;
    float4 acc[RT][CT];
    #pragma unroll
    for (int i = 0; i < RT; i++)
        #pragma unroll
        for (int g = 0; g < CT; g++) acc[i][g] = make_float4(0.f, 0.f, 0.f, 0.f);

    // Pass 1: Gs @ Wk (Ws streamed in 32-row chunks; zero-fill beyond K1)
    for (int k0 = 0; k0 < K1; k0 += 32) {
        #pragma unroll
        for (int j = 0; j < 32 * COUT / 256; j++) {
            int idx = tid + j * 256;
            int kk = idx / COUT, cc = idx - kk * COUT;
            int k = k0 + kk;
            Ws[kk * COUT + cc] = (k < K1) ? Wk[(long)k * COUT + cc] : 0.f;
        }
        __syncthreads();
        #pragma unroll
        for (int kq = 0; kq < 8; kq++) {
            float4 a[RT];
            #pragma unroll
            for (int i = 0; i < RT; i++)
                a[i] = *(const float4*)&Gs[(long)(ty * RT + i) * K1P + k0 + kq * 4];
            float4 b[4][CT];
            #pragma unroll
            for (int t = 0; t < 4; t++)
                #pragma unroll
                for (int g = 0; g < CT; g++)
                    b[t][g] = *(const float4*)&Ws[(kq * 4 + t) * COUT + g * 64 + tx * 4];
            #pragma unroll
            for (int i = 0; i < RT; i++) {
                float av[4] = {a[i].x, a[i].y, a[i].z, a[i].w};
                #pragma unroll
                for (int t = 0; t < 4; t++)
                    #pragma unroll
                    for (int g = 0; g < CT; g++) {
                        acc[i][g].x += av[t] * b[t][g].x;
                        acc[i][g].y += av[t] * b[t][g].y;
                        acc[i][g].z += av[t] * b[t][g].z;
                        acc[i][g].w += av[t] * b[t][g].w;
                    }
            }
        }
        __syncthreads();
    }

    // scale by 1/deg
    #pragma unroll
    for (int i = 0; i < RT; i++) {
        float inv = sDeg[ty * RT + i];
        #pragma unroll
        for (int g = 0; g < CT; g++) {
            acc[i][g].x *= inv; acc[i][g].y *= inv;
            acc[i][g].z *= inv; acc[i][g].w *= inv;
        }
    }

    // Pass 2: Fs @ Wr
    for (int k0 = 0; k0 < CIN; k0 += 32) {
        #pragma unroll
        for (int j = 0; j < 32 * COUT / 256; j++) {
            int idx = tid + j * 256;
            int kk = idx / COUT, cc = idx - kk * COUT;
            int k = k0 + kk;
            Ws[kk * COUT + cc] = (k < CIN) ? Wr[(long)k * COUT + cc] : 0.f;
        }
        __syncthreads();
        #pragma unroll
        for (int kq = 0; kq < 8; kq++) {
            if (k0 + kq * 4 >= CINP) break;   // Fs row exhausted
            float4 a[RT];
            #pragma unroll
            for (int i = 0; i < RT; i++)
                a[i] = *(const float4*)&Fs[(ty * RT + i) * CINP + k0 + kq * 4];
            float4 b[4][CT];
            #pragma unroll
            for (int t = 0; t < 4; t++)
                #pragma unroll
                for (int g = 0; g < CT; g++)
                    b[t][g] = *(const float4*)&Ws[(kq * 4 + t) * COUT + g * 64 + tx * 4];
            #pragma unroll
            for (int i = 0; i < RT; i++) {
                float av[4] = {a[i].x, a[i].y, a[i].z, a[i].w};
                // mask pad columns (Fs pad is garbage)
                #pragma unroll
                for (int t = 0; t < 4; t++) {
                    if (k0 + kq * 4 + t >= CIN) av[t] = 0.f;
                    #pragma unroll
                    for (int g = 0; g < CT; g++) {
                        acc[i][g].x += av[t] * b[t][g].x;
                        acc[i][g].y += av[t] * b[t][g].y;
                        acc[i][g].z += av[t] * b[t][g].z;
                        acc[i][g].w += av[t] * b[t][g].w;
                    }
                }
            }
        }
        __syncthreads();
    }

    // ---- Epilogue ----
    #pragma unroll
    for (int i = 0; i < RT; i++) {
        int v = v0 + ty * RT + i;
        long cl = 0;
        float px = 0.f, py = 0.f, pz = 0.f;
        if (POOL != 0) {
            px = pos[(long)v * 3 + 0];
            py = pos[(long)v * 3 + 1];
            pz = pos[(long)v * 3 + 2];
            int b_ = v / cellsPrev;
            int ix = min(max((int)floorf(px * nx), 0), nx - 1);
            int iy = min(max((int)floorf(py * ny), 0), ny - 1);
            int it = min(max((int)floorf(pz * nt), 0), nt - 1);
            cl = (((long)b_ * nx + ix) * ny + iy) * nt + it;
        }
        #pragma unroll
        for (int g = 0; g < CT; g++) {
            int col0 = g * 64 + tx * 4;
            float vals[4] = {acc[i][g].x, acc[i][g].y, acc[i][g].z, acc[i][g].w};
            #pragma unroll
            for (int u = 0; u < 4; u++) {
                int col = col0 + u;
                float val = fmaxf(vals[u] + bias[col], 0.f);
                if (WOUT) out[(long)v * COUT + col] = val;
                if (POOL == 1)
                    atomicMax((int*)(fcN + cl * (COUT + 2) + col), __float_as_int(val));
                else if (POOL == 2)
                    atomicAdd(fcN + cl * (COUT + 2) + col, val);
            }
        }
        if (POOL != 0 && tx == 0) {
            atomicAdd(posSum + cl * 3 + 0, px);
            atomicAdd(posSum + cl * 3 + 1, py);
            atomicAdd(posSum + cl * 3 + 2, pz);
            atomicAdd(cntPool + cl, 1.0f);
        }
    }
}

// smem sizes per instantiation (floats)
__host__ __device__ constexpr long smF(int CIN, int COUT, int TV) {
    return (long)TV * (8 * CIN + 4) + (long)TV * cinp_of(CIN) + 32L * COUT + TV;
}
constexpr int SM_L2 = (int)(smF(18, 64, 64) * 4);
constexpr int SM_L3 = (int)(smF(66, 128, 32) * 4);
constexpr int SM_L45 = (int)(smF(130, 128, 16) * 4);

// ---------------------------------------------------------------------------
// Launch
// ---------------------------------------------------------------------------
static inline int cdiv(long a, long b) { return (int)((a + b - 1) / b); }

extern "C" void kernel_launch(void* const* d_in, const int* in_sizes, int n_in,
                              void* d_out, int out_size) {
    const float* x    = (const float*)d_in[0];
    const float* pos0 = (const float*)d_in[1];
    const int*   batch = (const int*)d_in[2];
    const int* e0 = (const int*)d_in[3];
    const int* e1 = (const int*)d_in[4];
    const int* e2 = (const int*)d_in[5];
    const int* e3 = (const int*)d_in[6];
    const int* e4 = (const int*)d_in[7];
    const float* W1 = (const float*)d_in[8];
    const float* R1 = (const float*)d_in[9];
    const float* b1 = (const float*)d_in[10];
    const float* W2 = (const float*)d_in[11];
    const float* R2 = (const float*)d_in[12];
    const float* b2 = (const float*)d_in[13];
    const float* W3 = (const float*)d_in[14];
    const float* R3 = (const float*)d_in[15];
    const float* b3 = (const float*)d_in[16];
    const float* W4 = (const float*)d_in[17];
    const float* R4 = (const float*)d_in[18];
    const float* b4 = (const float*)d_in[19];
    const float* W5 = (const float*)d_in[20];
    const float* R5 = (const float*)d_in[21];
    const float* b5 = (const float*)d_in[22];
    float* out = (float*)d_out;

    float* buf;
    cudaGetSymbolAddress((void**)&buf, g_buf);
    int* ip;
    cudaGetSymbolAddress((void**)&ip, g_csr);
    int* cnt = ip + I_CNT;
    int* row = ip + I_ROW;
    int* cur = ip + I_CUR;
    int* ebin = ip + I_EBIN;
    int* bs = ip + I_BS;
    int* bo = ip + I_BO;

    cudaFuncSetAttribute(spline_fused_kernel<18, 64, 64, 1, false>,
                         cudaFuncAttributeMaxDynamicSharedMemorySize, SM_L2);
    cudaFuncSetAttribute(spline_fused_kernel<66, 128, 32, 1, false>,
                         cudaFuncAttributeMaxDynamicSharedMemorySize, SM_L3);
    cudaFuncSetAttribute(spline_fused_kernel<130, 128, 16, 2, true>,
                         cudaFuncAttributeMaxDynamicSharedMemorySize, SM_L45);
    cudaFuncSetAttribute(spline_fused_kernel<130, 128, 16, 0, true>,
                         cudaFuncAttributeMaxDynamicSharedMemorySize, SM_L45);

    Batch5 P;
    P.e[0] = e0; P.e[1] = e1; P.e[2] = e2; P.e[3] = e3; P.e[4] = e4;
    P.E[0] = NE0; P.E[1] = NE1; P.E[2] = NE2; P.E[3] = NE3; P.E[4] = NE4;
    P.voff[0] = VOFF0; P.voff[1] = VOFF1; P.voff[2] = VOFF2;
    P.voff[3] = VOFF3; P.voff[4] = VOFF4;

    init_kernel<<<512, 256>>>(buf, cnt, pos0, x);

    int hg = cdiv(NE0 / 4, 4 * 256);
    hist5_kernel<<<dim3(hg, 5), 256>>>(P, cnt);
    int nb = cdiv(TOTV, 2048);
    scan1_kernel<<<nb, 256>>>(cnt, row, cur, bs, (int)TOTV);
    scan1_kernel<<<1, 256>>>(bs, bo, nullptr, nullptr, nb);
    scan_add_kernel<<<nb, 256>>>(row, cur, bo, (int)TOTV);
    bin5_kernel<<<dim3(hg, 5), 256>>>(P, cur, ebin);

    // ---------------- Layer 1 ----------------
    spline1_fused_kernel<<<cdiv(NV0, 256), 256>>>(row + VOFF0, cnt + VOFF0, ebin,
        (const float4*)(buf + O_PXA), batch, W1, R1, b1,
        buf + O_FC1, buf + O_P1P, buf + O_CNT1, (int)NV0);
    finalize_kernel<16><<<cdiv(NV1, 256), 256>>>(buf + O_FC1, buf + O_P1P,
        buf + O_CNT1, (int)NV1, 0);

    // ---------------- Layer 2 ----------------
    spline_fused_kernel<18, 64, 64, 1, false><<<cdiv(NV1, 64), 256, SM_L2>>>(
        row + VOFF1, cnt + VOFF1, ebin, buf + O_P1P, buf + O_FC1,
        W2, R2, b2, nullptr, (int)NV1, 10.0f,
        64 * 48 * 8, 32, 24, 4, buf + O_FC2, buf + O_P2P, buf + O_CNT2);
    finalize_kernel<64><<<cdiv(NV2, 256), 256>>>(buf + O_FC2, buf + O_P2P,
        buf + O_CNT2, (int)NV2, 0);

    // ---------------- Layer 3 ----------------
    spline_fused_kernel<66, 128, 32, 1, false><<<cdiv(NV2, 32), 256, SM_L3>>>(
        row + VOFF2, cnt + VOFF2, ebin, buf + O_P2P, buf + O_FC2,
        W3, R3, b3, nullptr, (int)NV2, 6.0f,
        32 * 24 * 4, 16, 12, 2, buf + O_FC3, buf + O_P3P, buf + O_CNT3);
    finalize_kernel<128><<<cdiv(NV3, 256), 256>>>(buf + O_FC3, buf + O_P3P,
        buf + O_CNT3, (int)NV3, 0);

    // ---------------- Layer 4 ----------------
    spline_fused_kernel<130, 128, 16, 2, true><<<cdiv(NV3, 16), 256, SM_L45>>>(
        row + VOFF3, cnt + VOFF3, ebin, buf + O_P3P, buf + O_FC3,
        W4, R4, b4, out, (int)NV3, 3.0f,
        16 * 12 * 2, 8, 6, 1, buf + O_FC4, buf + O_P4P, buf + O_CNT4);
    finalize_kernel<128><<<cdiv(NV4, 256), 256>>>(buf + O_FC4, buf + O_P4P,
        buf + O_CNT4, (int)NV4, 1);

    // ---------------- Layer 5 ----------------
    spline_fused_kernel<130, 128, 16, 0, true><<<cdiv(NV4, 16), 256, SM_L45>>>(
        row + VOFF4, cnt + VOFF4, ebin, buf + O_P4P, buf + O_FC4,
        W5, R5, b5, out + NV3 * 128, (int)NV4, 1.5f,
        1, 1, 1, 1, nullptr, nullptr, nullptr);
}

// round 8
// speedup vs baseline: 2.4222x; 1.0373x over previous
#include <cuda_runtime.h>
#include <cuda_bf16.h>

// ---------------------------------------------------------------------------
// Problem constants
// ---------------------------------------------------------------------------
constexpr long NV0 = 300000, NV1 = 98304, NV2 = 12288, NV3 = 1536, NV4 = 192;
constexpr long NE0 = 3600000, NE1 = 786432, NE2 = 196608, NE3 = 24576, NE4 = 3072;
constexpr long TOTV = NV0 + NV1 + NV2 + NV3 + NV4;
constexpr long TOTE = NE0 + NE1 + NE2 + NE3 + NE4;

// ---------------------------------------------------------------------------
// Float scratch. Feature rows now carry pos: [feats C, px, py, pz] = C+3 wide
// (= CIN+1 where CIN = C+2 includes px,py for the root term).
// Zero-region first: fc rows + posSum + pool counts.
// ---------------------------------------------------------------------------
constexpr long O_FC1 = 0;                      // [NV1, 19]
constexpr long O_FC2 = O_FC1 + NV1 * 19;       // [NV2, 67]
constexpr long O_FC3 = O_FC2 + NV2 * 67;       // [NV3, 131]
constexpr long O_FC4 = O_FC3 + NV3 * 131;      // [NV4, 131]
constexpr long O_P1P = O_FC4 + NV4 * 131;
constexpr long O_P2P = O_P1P + NV1 * 3;
constexpr long O_P3P = O_P2P + NV2 * 3;
constexpr long O_P4P = O_P3P + NV3 * 3;
constexpr long O_CNT1 = O_P4P + NV4 * 3;
constexpr long O_CNT2 = O_CNT1 + NV1;
constexpr long O_CNT3 = O_CNT2 + NV2;
constexpr long O_CNT4 = O_CNT3 + NV3;
constexpr long ZERO_N0 = O_CNT4 + NV4;
constexpr long ZERO_N = (ZERO_N0 + 3) & ~3L;   // zeroed each run (mult of 4)
constexpr long O_PXA = ZERO_N;                 // [NV0] float4
constexpr long TOTAL_N = O_PXA + NV0 * 4;

__device__ __align__(16) float g_buf[TOTAL_N];

// Int scratch: concatenated CSR over all 5 layers.
constexpr long I_CNT = 0;
constexpr long I_ROW = I_CNT + TOTV;
constexpr long I_CUR = I_ROW + TOTV;
constexpr long I_EBIN = I_CUR + TOTV;
constexpr long I_BS  = I_EBIN + TOTE;
constexpr long I_BO  = I_BS + 2048;
constexpr long TOTAL_I = I_BO + 2048;

__device__ __align__(16) int g_csr[TOTAL_I];

constexpr int VOFF0 = 0;
constexpr int VOFF1 = (int)NV0;
constexpr int VOFF2 = (int)(NV0 + NV1);
constexpr int VOFF3 = (int)(NV0 + NV1 + NV2);
constexpr int VOFF4 = (int)(NV0 + NV1 + NV2 + NV3);

struct Batch5 {
    const int* e[5];
    long E[5];
    int voff[5];
};

// ---------------------------------------------------------------------------
// init: zero float region, zero CSR counts, build pxa = (pos, x)
// ---------------------------------------------------------------------------
__global__ void init_kernel(float* __restrict__ buf, int* __restrict__ cnt,
                            const float* __restrict__ pos, const float* __restrict__ x) {
    long t = (long)blockIdx.x * blockDim.x + threadIdx.x;
    long T = (long)gridDim.x * blockDim.x;
    float4 z = make_float4(0.f, 0.f, 0.f, 0.f);
    float4* b4 = reinterpret_cast<float4*>(buf);
    for (long i = t; i < ZERO_N / 4; i += T) b4[i] = z;
    for (long i = t; i < TOTV; i += T) cnt[i] = 0;
    float4* pxa = reinterpret_cast<float4*>(buf + O_PXA);
    for (long v = t; v < NV0; v += T)
        pxa[v] = make_float4(pos[v * 3], pos[v * 3 + 1], pos[v * 3 + 2], x[v]);
}

// ---------------------------------------------------------------------------
// Batched CSR build.
// ---------------------------------------------------------------------------
__global__ void __launch_bounds__(256)
hist5_kernel(Batch5 p, int* __restrict__ cnt) {
    int L = blockIdx.y;
    long n4 = p.E[L] >> 2;
    const int4* dst4 = reinterpret_cast<const int4*>(p.e[L] + p.E[L]);
    int* c = cnt + p.voff[L];
    long T = (long)gridDim.x * blockDim.x;
    long t = (long)blockIdx.x * blockDim.x + threadIdx.x;
    int4 d[4]; bool g[4];
    #pragma unroll
    for (int u = 0; u < 4; u++) {
        long i = t + (long)u * T;
        g[u] = i < n4;
        if (g[u]) d[u] = dst4[i];
    }
    #pragma unroll
    for (int u = 0; u < 4; u++) {
        if (g[u]) {
            atomicAdd(&c[d[u].x], 1);
            atomicAdd(&c[d[u].y], 1);
            atomicAdd(&c[d[u].z], 1);
            atomicAdd(&c[d[u].w], 1);
        }
    }
}

__global__ void scan1_kernel(const int* __restrict__ in, int* __restrict__ out,
                             int* __restrict__ out2, int* __restrict__ bsums, int n) {
    __shared__ int tot[256];
    int tid = threadIdx.x;
    long base = (long)blockIdx.x * 2048 + (long)tid * 8;
    int v[8]; int sum = 0;
    #pragma unroll
    for (int j = 0; j < 8; j++) { v[j] = (base + j < n) ? in[base + j] : 0; sum += v[j]; }
    tot[tid] = sum;
    __syncthreads();
    #pragma unroll
    for (int off = 1; off < 256; off <<= 1) {
        int t = (tid >= off) ? tot[tid - off] : 0;
        __syncthreads();
        tot[tid] += t;
        __syncthreads();
    }
    int run = (tid == 0) ? 0 : tot[tid - 1];
    #pragma unroll
    for (int j = 0; j < 8; j++) {
        if (base + j < n) {
            out[base + j] = run;
            if (out2) out2[base + j] = run;
        }
        run += v[j];
    }
    if (bsums && tid == 255) bsums[blockIdx.x] = tot[255];
}

__global__ void scan_add_kernel(int* __restrict__ out, int* __restrict__ out2,
                                const int* __restrict__ boffs, int n) {
    int add = boffs[blockIdx.x];
    long base = (long)blockIdx.x * 2048 + (long)threadIdx.x * 8;
    #pragma unroll
    for (int j = 0; j < 8; j++)
        if (base + j < n) { out[base + j] += add; out2[base + j] += add; }
}

__global__ void __launch_bounds__(256)
bin5_kernel(Batch5 p, int* __restrict__ cur, int* __restrict__ ebin) {
    int L = blockIdx.y;
    long n4 = p.E[L] >> 2;
    const int4* src4 = reinterpret_cast<const int4*>(p.e[L]);
    const int4* dst4 = reinterpret_cast<const int4*>(p.e[L] + p.E[L]);
    int* cu = cur + p.voff[L];
    long T = (long)gridDim.x * blockDim.x;
    long t = (long)blockIdx.x * blockDim.x + threadIdx.x;
    int4 s[4], d[4]; bool g[4];
    #pragma unroll
    for (int u = 0; u < 4; u++) {
        long i = t + (long)u * T;
        g[u] = i < n4;
        if (g[u]) { s[u] = src4[i]; d[u] = dst4[i]; }
    }
    #pragma unroll
    for (int u = 0; u < 4; u++) {
        if (g[u]) {
            int p0 = atomicAdd(&cu[d[u].x], 1);
            int p1 = atomicAdd(&cu[d[u].y], 1);
            int p2 = atomicAdd(&cu[d[u].z], 1);
            int p3 = atomicAdd(&cu[d[u].w], 1);
            ebin[p0] = s[u].x;
            ebin[p1] = s[u].y;
            ebin[p2] = s[u].z;
            ebin[p3] = s[u].w;
        }
    }
}

// ---------------------------------------------------------------------------
// Basis helper
// ---------------------------------------------------------------------------
__device__ __forceinline__ void basis8(float p0, float p1, float p2, float* b) {
    float q0 = 1.f - p0, q1 = 1.f - p1, q2 = 1.f - p2;
    float b00 = q0 * q1, b01 = p0 * q1, b10 = q0 * p1, b11 = p0 * p1;
    b[0] = b00 * q2; b[1] = b01 * q2; b[2] = b10 * q2; b[3] = b11 * q2;
    b[4] = b00 * p2; b[5] = b01 * p2; b[6] = b10 * p2; b[7] = b11 * p2;
}

// ---------------------------------------------------------------------------
// Layer 1 fused: gather (4-edge pipeline) + 24x16 GEMM + maxpool into fc1.
// ---------------------------------------------------------------------------
__device__ __forceinline__ void s1_accum(float4 sp, float dx, float dy, float dz,
                                         float* G) {
    float p0 = __saturatef((dx - sp.x) * 20.0f + 0.5f);
    float p1 = __saturatef((dy - sp.y) * 20.0f + 0.5f);
    float p2 = __saturatef((dz - sp.z) * 20.0f + 0.5f);
    float b[8]; basis8(p0, p1, p2, b);
    #pragma unroll
    for (int s8 = 0; s8 < 8; s8++) {
        G[s8 * 3 + 0] += b[s8] * sp.w;
        G[s8 * 3 + 1] += b[s8] * sp.x;
        G[s8 * 3 + 2] += b[s8] * sp.y;
    }
}

__global__ void __launch_bounds__(256)
spline1_fused_kernel(const int* __restrict__ rowptr, const int* __restrict__ cnt,
                     const int* __restrict__ ebin,
                     const float4* __restrict__ pxa, const int* __restrict__ batch,
                     const float* __restrict__ Wk, const float* __restrict__ Wr,
                     const float* __restrict__ bias,
                     float* __restrict__ fc1, float* __restrict__ posSum,
                     float* __restrict__ cntPool, int V) {
    __shared__ float sWk[24][16];
    __shared__ float sWr[3][16];
    __shared__ float sb[16];
    int tid = threadIdx.x;
    for (int i = tid; i < 24 * 16; i += 256) sWk[i / 16][i % 16] = Wk[i];
    if (tid < 48) sWr[tid / 16][tid % 16] = Wr[tid];
    if (tid < 16) sb[tid] = bias[tid];
    __syncthreads();
    int v = blockIdx.x * 256 + tid;
    if (v >= V) return;

    float G[24];
    #pragma unroll
    for (int k = 0; k < 24; k++) G[k] = 0.f;

    float4 me = pxa[v];
    float dx = me.x, dy = me.y, dz = me.z;
    int start = rowptr[v];
    int deg = cnt[v];
    int j = 0;
    for (; j + 4 <= deg; j += 4) {
        int s0 = ebin[start + j + 0];
        int s1 = ebin[start + j + 1];
        int s2 = ebin[start + j + 2];
        int s3 = ebin[start + j + 3];
        float4 a0 = pxa[s0];
        float4 a1 = pxa[s1];
        float4 a2 = pxa[s2];
        float4 a3 = pxa[s3];
        s1_accum(a0, dx, dy, dz, G);
        s1_accum(a1, dx, dy, dz, G);
        s1_accum(a2, dx, dy, dz, G);
        s1_accum(a3, dx, dy, dz, G);
    }
    for (; j < deg; j++) {
        float4 a0 = pxa[ebin[start + j]];
        s1_accum(a0, dx, dy, dz, G);
    }

    float acc[16];
    #pragma unroll
    for (int c = 0; c < 16; c++) acc[c] = 0.f;
    #pragma unroll
    for (int k = 0; k < 24; k++) {
        float g = G[k];
        #pragma unroll
        for (int c = 0; c < 16; c++) acc[c] += g * sWk[k][c];
    }
    float inv = 1.f / fmaxf((float)deg, 1.f);

    int b_ = batch[v];
    int ix = min(max((int)floorf(dx * 64.f), 0), 63);
    int iy = min(max((int)floorf(dy * 48.f), 0), 47);
    int it = min(max((int)floorf(dz * 8.f), 0), 7);
    long cl = (((long)b_ * 64 + ix) * 48 + iy) * 8 + it;
    float* fcrow = fc1 + cl * 19;

    #pragma unroll
    for (int c = 0; c < 16; c++) {
        float val = acc[c] * inv + me.w * sWr[0][c] + dx * sWr[1][c]
                  + dy * sWr[2][c] + sb[c];
        val = fmaxf(val, 0.f);
        atomicMax((int*)(fcrow + c), __float_as_int(val));
    }
    atomicAdd(posSum + cl * 3 + 0, dx);
    atomicAdd(posSum + cl * 3 + 1, dy);
    atomicAdd(posSum + cl * 3 + 2, dz);
    atomicAdd(cntPool + cl, 1.0f);
}

// ---------------------------------------------------------------------------
// finalize: row width C+3; writes px,py,pz into row[C..C+2].
// ---------------------------------------------------------------------------
template <int C>
__global__ void finalize_kernel(float* __restrict__ fc, const float* __restrict__ posSum,
                                const float* __restrict__ cnt, int V, int isMean) {
    int v = blockIdx.x * blockDim.x + threadIdx.x;
    if (v >= V) return;
    float cn = fmaxf(cnt[v], 1.0f);
    float inv = 1.0f / cn;
    float px = posSum[(long)v * 3 + 0] * inv;
    float py = posSum[(long)v * 3 + 1] * inv;
    float pz = posSum[(long)v * 3 + 2] * inv;
    float* row = fc + (long)v * (C + 3);
    row[C] = px;
    row[C + 1] = py;
    row[C + 2] = pz;
    if (isMean)
        for (int k = 0; k < C; k++) row[k] *= inv;
}

// ---------------------------------------------------------------------------
// Fully fused layer (2..5): paired-edge pipelined gather into dynamic smem,
// then register-tiled GEMM + root + bias + relu + optional pool / out-write.
// featP rows: [feat CIN (incl px,py), pz] -> width W = CIN+1; src pos read
// from the SAME row as the features. POOL: 0 none, 1 max, 2 mean.
// ---------------------------------------------------------------------------
__host__ __device__ constexpr int pad4(int x) { return (x + 3) & ~3; }
__host__ __device__ constexpr int cinp_of(int CIN) {
    return pad4(CIN) + ((pad4(CIN) == CIN) ? 4 : 0);
}

template <int CIN, int COUT, int TV, int POOL, bool WOUT>
__global__ void __launch_bounds__(256)
spline_fused_kernel(const int* __restrict__ rowptr, const int* __restrict__ cnt,
                    const int* __restrict__ ebin,
                    const float* __restrict__ featP,  // [V, CIN+1]
                    const float* __restrict__ Wk, const float* __restrict__ Wr,
                    const float* __restrict__ bias,
                    float* __restrict__ out, int V, float inv2mv,
                    int cellsPrev, int nx, int ny, int nt,
                    float* __restrict__ fcN, float* __restrict__ posSum,
                    float* __restrict__ cntPool) {
    constexpr int W = CIN + 1;
    constexpr int K1 = 8 * CIN;
    constexpr int K1P = K1 + 4;
    constexpr int CINP = cinp_of(CIN);
    constexpr int NJ = (CIN + 31) / 32;
    constexpr int NPW = TV / 8;
    constexpr int RT = TV / 16;
    constexpr int CT = COUT / 64;

    extern __shared__ float sm[];
    float* Gs = sm;                      // [TV][K1P]
    float* Fs = Gs + TV * K1P;           // [TV][CINP]
    float* Ws = Fs + TV * CINP;          // [32][COUT]
    float* sDeg = Ws + 32 * COUT;        // [TV]

    int tid = threadIdx.x;
    int lane = tid & 31, warp = tid >> 5;
    int v0 = blockIdx.x * TV;

    // ---- Phase 1: paired-edge pipelined gather ----
    for (int t = 0; t < NPW; t++) {
        int n = warp * NPW + t;
        int v = v0 + n;
        const float* vrow = featP + (long)v * W;
        float dx = vrow[CIN - 2];
        float dy = vrow[CIN - 1];
        float dz = vrow[CIN];
        int start = rowptr[v];
        int deg = cnt[v];
        float Gacc[NJ][8];
        #pragma unroll
        for (int jj = 0; jj < NJ; jj++)
            #pragma unroll
            for (int s8 = 0; s8 < 8; s8++) Gacc[jj][s8] = 0.f;

        int j = 0;
        for (; j + 2 <= deg; j += 2) {
            int sA = ebin[start + j];
            int sB = ebin[start + j + 1];
            const float* rA = featP + (long)sA * W;
            const float* rB = featP + (long)sB * W;
            // issue all loads for both edges before consuming
            float fA[NJ], fB[NJ];
            #pragma unroll
            for (int jj = 0; jj < NJ; jj++) {
                int idx = lane + jj * 32;
                fA[jj] = (idx < CIN) ? rA[idx] : 0.f;
                fB[jj] = (idx < CIN) ? rB[idx] : 0.f;
            }
            float axp = rA[CIN - 2], ayp = rA[CIN - 1], azp = rA[CIN];
            float bxp = rB[CIN - 2], byp = rB[CIN - 1], bzp = rB[CIN];
            {
                float p0 = __saturatef((dx - axp) * inv2mv + 0.5f);
                float p1 = __saturatef((dy - ayp) * inv2mv + 0.5f);
                float p2 = __saturatef((dz - azp) * inv2mv + 0.5f);
                float b[8]; basis8(p0, p1, p2, b);
                #pragma unroll
                for (int s8 = 0; s8 < 8; s8++)
                    #pragma unroll
                    for (int jj = 0; jj < NJ; jj++) Gacc[jj][s8] += b[s8] * fA[jj];
            }
            {
                float p0 = __saturatef((dx - bxp) * inv2mv + 0.5f);
                float p1 = __saturatef((dy - byp) * inv2mv + 0.5f);
                float p2 = __saturatef((dz - bzp) * inv2mv + 0.5f);
                float b[8]; basis8(p0, p1, p2, b);
                #pragma unroll
                for (int s8 = 0; s8 < 8; s8++)
                    #pragma unroll
                    for (int jj = 0; jj < NJ; jj++) Gacc[jj][s8] += b[s8] * fB[jj];
            }
        }
        for (; j < deg; j++) {
            int s = ebin[start + j];
            const float* rA = featP + (long)s * W;
            float fA[NJ];
            #pragma unroll
            for (int jj = 0; jj < NJ; jj++) {
                int idx = lane + jj * 32;
                fA[jj] = (idx < CIN) ? rA[idx] : 0.f;
            }
            float p0 = __saturatef((dx - rA[CIN - 2]) * inv2mv + 0.5f);
            float p1 = __saturatef((dy - rA[CIN - 1]) * inv2mv + 0.5f);
            float p2 = __saturatef((dz - rA[CIN]) * inv2mv + 0.5f);
            float b[8]; basis8(p0, p1, p2, b);
            #pragma unroll
            for (int s8 = 0; s8 < 8; s8++)
                #pragma unroll
                for (int jj = 0; jj < NJ; jj++) Gacc[jj][s8] += b[s8] * fA[jj];
        }

        #pragma unroll
        for (int s8 = 0; s8 < 8; s8++)
            #pragma unroll
            for (int jj = 0; jj < NJ; jj++) {
                int idx = lane + jj * 32;
                if (idx < CIN) Gs[(long)n * K1P + s8 * CIN + idx] = Gacc[jj][s8];
            }
        #pragma unroll
        for (int jj = 0; jj < NJ; jj++) {
            int idx = lane + jj * 32;
            if (idx < CIN) Fs[n * CINP + idx] = vrow[idx];
        }
        if (lane == 0) sDeg[n] = 1.f / fmaxf((float)deg, 1.f);
    }
    __syncthreads();

    // ---- Phase 2: GEMM ----
    int tx = tid & 15, ty = tid >> 4;
    float4 acc[RT][CT];
    #pragma unroll
    for (int i = 0; i < RT; i++)
        #pragma unroll
        for (int g = 0; g < CT; g++) acc[i][g] = make_float4(0.f, 0.f, 0.f, 0.f);

    for (int k0 = 0; k0 < K1; k0 += 32) {
        #pragma unroll
        for (int j = 0; j < 32 * COUT / 256; j++) {
            int idx = tid + j * 256;
            int kk = idx / COUT, cc = idx - kk * COUT;
            int k = k0 + kk;
            Ws[kk * COUT + cc] = (k < K1) ? Wk[(long)k * COUT + cc] : 0.f;
        }
        __syncthreads();
        #pragma unroll
        for (int kq = 0; kq < 8; kq++) {
            float4 a[RT];
            #pragma unroll
            for (int i = 0; i < RT; i++)
                a[i] = *(const float4*)&Gs[(long)(ty * RT + i) * K1P + k0 + kq * 4];
            float4 b[4][CT];
            #pragma unroll
            for (int t = 0; t < 4; t++)
                #pragma unroll
                for (int g = 0; g < CT; g++)
                    b[t][g] = *(const float4*)&Ws[(kq * 4 + t) * COUT + g * 64 + tx * 4];
            #pragma unroll
            for (int i = 0; i < RT; i++) {
                float av[4] = {a[i].x, a[i].y, a[i].z, a[i].w};
                #pragma unroll
                for (int t = 0; t < 4; t++)
                    #pragma unroll
                    for (int g = 0; g < CT; g++) {
                        acc[i][g].x += av[t] * b[t][g].x;
                        acc[i][g].y += av[t] * b[t][g].y;
                        acc[i][g].z += av[t] * b[t][g].z;
                        acc[i][g].w += av[t] * b[t][g].w;
                    }
            }
        }
        __syncthreads();
    }

    #pragma unroll
    for (int i = 0; i < RT; i++) {
        float inv = sDeg[ty * RT + i];
        #pragma unroll
        for (int g = 0; g < CT; g++) {
            acc[i][g].x *= inv; acc[i][g].y *= inv;
            acc[i][g].z *= inv; acc[i][g].w *= inv;
        }
    }

    for (int k0 = 0; k0 < CIN; k0 += 32) {
        #pragma unroll
        for (int j = 0; j < 32 * COUT / 256; j++) {
            int idx = tid + j * 256;
            int kk = idx / COUT, cc = idx - kk * COUT;
            int k = k0 + kk;
            Ws[kk * COUT + cc] = (k < CIN) ? Wr[(long)k * COUT + cc] : 0.f;
        }
        __syncthreads();
        #pragma unroll
        for (int kq = 0; kq < 8; kq++) {
            if (k0 + kq * 4 >= CINP) break;
            float4 a[RT];
            #pragma unroll
            for (int i = 0; i < RT; i++)
                a[i] = *(const float4*)&Fs[(ty * RT + i) * CINP + k0 + kq * 4];
            float4 b[4][CT];
            #pragma unroll
            for (int t = 0; t < 4; t++)
                #pragma unroll
                for (int g = 0; g < CT; g++)
                    b[t][g] = *(const float4*)&Ws[(kq * 4 + t) * COUT + g * 64 + tx * 4];
            #pragma unroll
            for (int i = 0; i < RT; i++) {
                float av[4] = {a[i].x, a[i].y, a[i].z, a[i].w};
                #pragma unroll
                for (int t = 0; t < 4; t++) {
                    if (k0 + kq * 4 + t >= CIN) av[t] = 0.f;
                    #pragma unroll
                    for (int g = 0; g < CT; g++) {
                        acc[i][g].x += av[t] * b[t][g].x;
                        acc[i][g].y += av[t] * b[t][g].y;
                        acc[i][g].z += av[t] * b[t][g].z;
                        acc[i][g].w += av[t] * b[t][g].w;
                    }
                }
            }
        }
        __syncthreads();
    }

    // ---- Epilogue ----
    #pragma unroll
    for (int i = 0; i < RT; i++) {
        int v = v0 + ty * RT + i;
        long cl = 0;
        float px = 0.f, py = 0.f, pz = 0.f;
        if (POOL != 0) {
            const float* vrow = featP + (long)v * W;
            px = vrow[CIN - 2];
            py = vrow[CIN - 1];
            pz = vrow[CIN];
            int b_ = v / cellsPrev;
            int ix = min(max((int)floorf(px * nx), 0), nx - 1);
            int iy = min(max((int)floorf(py * ny), 0), ny - 1);
            int it = min(max((int)floorf(pz * nt), 0), nt - 1);
            cl = (((long)b_ * nx + ix) * ny + iy) * nt + it;
        }
        #pragma unroll
        for (int g = 0; g < CT; g++) {
            int col0 = g * 64 + tx * 4;
            float vals[4] = {acc[i][g].x, acc[i][g].y, acc[i][g].z, acc[i][g].w};
            #pragma unroll
            for (int u = 0; u < 4; u++) {
                int col = col0 + u;
                float val = fmaxf(vals[u] + bias[col], 0.f);
                if (WOUT) out[(long)v * COUT + col] = val;
                if (POOL == 1)
                    atomicMax((int*)(fcN + cl * (COUT + 3) + col), __float_as_int(val));
                else if (POOL == 2)
                    atomicAdd(fcN + cl * (COUT + 3) + col, val);
            }
        }
        if (POOL != 0 && tx == 0) {
            atomicAdd(posSum + cl * 3 + 0, px);
            atomicAdd(posSum + cl * 3 + 1, py);
            atomicAdd(posSum + cl * 3 + 2, pz);
            atomicAdd(cntPool + cl, 1.0f);
        }
    }
}

// smem sizes per instantiation (floats)
__host__ __device__ constexpr long smF(int CIN, int COUT, int TV) {
    return (long)TV * (8 * CIN + 4) + (long)TV * cinp_of(CIN) + 32L * COUT + TV;
}
constexpr int SM_L2 = (int)(smF(18, 64, 64) * 4);
constexpr int SM_L3 = (int)(smF(66, 128, 32) * 4);
constexpr int SM_L45 = (int)(smF(130, 128, 16) * 4);

// ---------------------------------------------------------------------------
// Launch
// ---------------------------------------------------------------------------
static inline int cdiv(long a, long b) { return (int)((a + b - 1) / b); }

extern "C" void kernel_launch(void* const* d_in, const int* in_sizes, int n_in,
                              void* d_out, int out_size) {
    const float* x    = (const float*)d_in[0];
    const float* pos0 = (const float*)d_in[1];
    const int*   batch = (const int*)d_in[2];
    const int* e0 = (const int*)d_in[3];
    const int* e1 = (const int*)d_in[4];
    const int* e2 = (const int*)d_in[5];
    const int* e3 = (const int*)d_in[6];
    const int* e4 = (const int*)d_in[7];
    const float* W1 = (const float*)d_in[8];
    const float* R1 = (const float*)d_in[9];
    const float* b1 = (const float*)d_in[10];
    const float* W2 = (const float*)d_in[11];
    const float* R2 = (const float*)d_in[12];
    const float* b2 = (const float*)d_in[13];
    const float* W3 = (const float*)d_in[14];
    const float* R3 = (const float*)d_in[15];
    const float* b3 = (const float*)d_in[16];
    const float* W4 = (const float*)d_in[17];
    const float* R4 = (const float*)d_in[18];
    const float* b4 = (const float*)d_in[19];
    const float* W5 = (const float*)d_in[20];
    const float* R5 = (const float*)d_in[21];
    const float* b5 = (const float*)d_in[22];
    float* out = (float*)d_out;

    float* buf;
    cudaGetSymbolAddress((void**)&buf, g_buf);
    int* ip;
    cudaGetSymbolAddress((void**)&ip, g_csr);
    int* cnt = ip + I_CNT;
    int* row = ip + I_ROW;
    int* cur = ip + I_CUR;
    int* ebin = ip + I_EBIN;
    int* bs = ip + I_BS;
    int* bo = ip + I_BO;

    cudaFuncSetAttribute(spline_fused_kernel<18, 64, 64, 1, false>,
                         cudaFuncAttributeMaxDynamicSharedMemorySize, SM_L2);
    cudaFuncSetAttribute(spline_fused_kernel<66, 128, 32, 1, false>,
                         cudaFuncAttributeMaxDynamicSharedMemorySize, SM_L3);
    cudaFuncSetAttribute(spline_fused_kernel<130, 128, 16, 2, true>,
                         cudaFuncAttributeMaxDynamicSharedMemorySize, SM_L45);
    cudaFuncSetAttribute(spline_fused_kernel<130, 128, 16, 0, true>,
                         cudaFuncAttributeMaxDynamicSharedMemorySize, SM_L45);

    Batch5 P;
    P.e[0] = e0; P.e[1] = e1; P.e[2] = e2; P.e[3] = e3; P.e[4] = e4;
    P.E[0] = NE0; P.E[1] = NE1; P.E[2] = NE2; P.E[3] = NE3; P.E[4] = NE4;
    P.voff[0] = VOFF0; P.voff[1] = VOFF1; P.voff[2] = VOFF2;
    P.voff[3] = VOFF3; P.voff[4] = VOFF4;

    init_kernel<<<512, 256>>>(buf, cnt, pos0, x);

    int hg = cdiv(NE0 / 4, 4 * 256);
    hist5_kernel<<<dim3(hg, 5), 256>>>(P, cnt);
    int nb = cdiv(TOTV, 2048);
    scan1_kernel<<<nb, 256>>>(cnt, row, cur, bs, (int)TOTV);
    scan1_kernel<<<1, 256>>>(bs, bo, nullptr, nullptr, nb);
    scan_add_kernel<<<nb, 256>>>(row, cur, bo, (int)TOTV);
    bin5_kernel<<<dim3(hg, 5), 256>>>(P, cur, ebin);

    // ---------------- Layer 1 ----------------
    spline1_fused_kernel<<<cdiv(NV0, 256), 256>>>(row + VOFF0, cnt + VOFF0, ebin,
        (const float4*)(buf + O_PXA), batch, W1, R1, b1,
        buf + O_FC1, buf + O_P1P, buf + O_CNT1, (int)NV0);
    finalize_kernel<16><<<cdiv(NV1, 256), 256>>>(buf + O_FC1, buf + O_P1P,
        buf + O_CNT1, (int)NV1, 0);

    // ---------------- Layer 2 ----------------
    spline_fused_kernel<18, 64, 64, 1, false><<<cdiv(NV1, 64), 256, SM_L2>>>(
        row + VOFF1, cnt + VOFF1, ebin, buf + O_FC1,
        W2, R2, b2, nullptr, (int)NV1, 10.0f,
        64 * 48 * 8, 32, 24, 4, buf + O_FC2, buf + O_P2P, buf + O_CNT2);
    finalize_kernel<64><<<cdiv(NV2, 256), 256>>>(buf + O_FC2, buf + O_P2P,
        buf + O_CNT2, (int)NV2, 0);

    // ---------------- Layer 3 ----------------
    spline_fused_kernel<66, 128, 32, 1, false><<<cdiv(NV2, 32), 256, SM_L3>>>(
        row + VOFF2, cnt + VOFF2, ebin, buf + O_FC2,
        W3, R3, b3, nullptr, (int)NV2, 6.0f,
        32 * 24 * 4, 16, 12, 2, buf + O_FC3, buf + O_P3P, buf + O_CNT3);
    finalize_kernel<128><<<cdiv(NV3, 256), 256>>>(buf + O_FC3, buf + O_P3P,
        buf + O_CNT3, (int)NV3, 0);

    // ---------------- Layer 4 ----------------
    spline_fused_kernel<130, 128, 16, 2, true><<<cdiv(NV3, 16), 256, SM_L45>>>(
        row + VOFF3, cnt + VOFF3, ebin, buf + O_FC3,
        W4, R4, b4, out, (int)NV3, 3.0f,
        16 * 12 * 2, 8, 6, 1, buf + O_FC4, buf + O_P4P, buf + O_CNT4);
    finalize_kernel<128><<<cdiv(NV4, 256), 256>>>(buf + O_FC4, buf + O_P4P,
        buf + O_CNT4, (int)NV4, 1);

    // ---------------- Layer 5 ----------------
    spline_fused_kernel<130, 128, 16, 0, true><<<cdiv(NV4, 16), 256, SM_L45>>>(
        row + VOFF4, cnt + VOFF4, ebin, buf + O_FC4,
        W5, R5, b5, out + NV3 * 128, (int)NV4, 1.5f,
        1, 1, 1, 1, nullptr, nullptr, nullptr);
}